// round 1
// baseline (speedup 1.0000x reference)
#include <cuda_runtime.h>
#include <math.h>

#define SLEN 2048
#define DM   1024
#define NHEAD 16
#define HD   64
#define BATCH 2
#define NROWS (BATCH*SLEN)   // 4096
#define PADF 68              // padded row stride (floats) for flash smem tiles

// Scratch (device globals; no allocation allowed)
__device__ float g_q[(size_t)BATCH*NHEAD*SLEN*HD];
__device__ float g_k[(size_t)BATCH*NHEAD*SLEN*HD];
__device__ float g_v[(size_t)BATCH*NHEAD*SLEN*HD];
__device__ float g_attn[(size_t)NROWS*DM];

// ---------------------------------------------------------------------------
// GEMM 1: qkv = x[4096,1024] @ W_qkv[1024,3072], fused RoPE + scatter to
// g_q/g_k/g_v in [B*H, S, hd] layout. 128x128x8 tile, 8x8 microtile, 256 thr.
// ---------------------------------------------------------------------------
__global__ __launch_bounds__(256) void qkv_gemm_kernel(
    const float* __restrict__ x, const float* __restrict__ W,
    const float* __restrict__ rc, const float* __restrict__ rs)
{
    __shared__ float As[8][128];   // As[k][row]
    __shared__ float Bs[8][128];   // Bs[k][col]
    const int tid  = threadIdx.x;
    const int row0 = blockIdx.y * 128;
    const int col0 = blockIdx.x * 128;
    const int ty = tid >> 4, tx = tid & 15;       // 16x16 thread grid
    const int ar  = tid >> 1, akk = (tid & 1) * 4; // A loader: row, k-offset
    const int bkk = tid >> 5, bc  = (tid & 31) * 4; // B loader: k-row, col

    float acc[8][8];
    #pragma unroll
    for (int i = 0; i < 8; i++)
        #pragma unroll
        for (int j = 0; j < 8; j++) acc[i][j] = 0.f;

    const float* Ap = x + (size_t)(row0 + ar) * DM + akk;

    for (int k0 = 0; k0 < DM; k0 += 8) {
        float4 av = *(const float4*)(Ap + k0);
        float4 bv = *(const float4*)(W + (size_t)(k0 + bkk) * 3072 + col0 + bc);
        __syncthreads();
        As[akk + 0][ar] = av.x; As[akk + 1][ar] = av.y;
        As[akk + 2][ar] = av.z; As[akk + 3][ar] = av.w;
        *(float4*)&Bs[bkk][bc] = bv;
        __syncthreads();
        #pragma unroll
        for (int kk = 0; kk < 8; kk++) {
            float a[8], bb[8];
            *(float4*)(a)      = *(const float4*)&As[kk][ty * 8];
            *(float4*)(a + 4)  = *(const float4*)&As[kk][ty * 8 + 4];
            *(float4*)(bb)     = *(const float4*)&Bs[kk][tx * 8];
            *(float4*)(bb + 4) = *(const float4*)&Bs[kk][tx * 8 + 4];
            #pragma unroll
            for (int i = 0; i < 8; i++)
                #pragma unroll
                for (int j = 0; j < 8; j++)
                    acc[i][j] = fmaf(a[i], bb[j], acc[i][j]);
        }
    }

    // Epilogue: decode (part, head, dim), apply RoPE for q/k, scatter.
    const int gc   = col0 + tx * 8;
    const int part = gc >> 10;          // 0=q, 1=k, 2=v (block never straddles)
    const int cp   = gc & 1023;
    const int h    = cp >> 6;
    const int dd0  = cp & 63;
    float* dst = (part == 0) ? g_q : (part == 1) ? g_k : g_v;

    #pragma unroll
    for (int i = 0; i < 8; i++) {
        const int grow = row0 + ty * 8 + i;
        const int b = grow >> 11, s = grow & 2047;
        float* o = dst + ((size_t)(b * NHEAD + h) * SLEN + s) * HD + dd0;
        if (part < 2) {
            #pragma unroll
            for (int p = 0; p < 4; p++) {
                const int pi = (dd0 >> 1) + p;
                const float c  = rc[s * 32 + pi];
                const float sn = rs[s * 32 + pi];
                const float v1 = acc[i][2 * p], v2 = acc[i][2 * p + 1];
                float2 r2;
                r2.x = v1 * c - v2 * sn;
                r2.y = v1 * sn + v2 * c;
                *(float2*)(o + 2 * p) = r2;
            }
        } else {
            float4 r4;
            r4.x = acc[i][0]; r4.y = acc[i][1]; r4.z = acc[i][2]; r4.w = acc[i][3];
            *(float4*)(o) = r4;
            r4.x = acc[i][4]; r4.y = acc[i][5]; r4.z = acc[i][6]; r4.w = acc[i][7];
            *(float4*)(o + 4) = r4;
        }
    }
}

// ---------------------------------------------------------------------------
// FlashAttention-2 style causal attention, fp32.
// Block: 64 queries, 128 threads. Key tiles of 64. hd = 64.
// Both matmul phases register-tiled (4x8 per thread over a 16x8 thread grid).
// ---------------------------------------------------------------------------
__global__ __launch_bounds__(128) void flash_kernel()
{
    extern __shared__ float sm[];
    float* QsT  = sm;                 // [d][r] 64x68
    float* KsT  = QsT + 64 * PADF;    // [d][c]
    float* Vs   = KsT + 64 * PADF;    // [j][d]
    float* Ss   = Vs  + 64 * PADF;    // [r][j]
    float* PsT  = Ss  + 64 * PADF;    // [j][r]
    float* mrow = PsT + 64 * PADF;    // [64]
    float* lrow = mrow + 64;          // [64]
    float* resc = lrow + 64;          // [64]

    const int tid = threadIdx.x;
    const int q0  = blockIdx.x * 64;
    const int bh  = blockIdx.y;

    const float* Qg  = g_q + ((size_t)bh * SLEN + q0) * HD;
    const float* Kg0 = g_k + (size_t)bh * SLEN * HD;
    const float* Vg0 = g_v + (size_t)bh * SLEN * HD;

    // Load Q tile transposed
    #pragma unroll
    for (int e = 0; e < 8; e++) {
        const int flat = tid * 4 + e * 512;
        const int r = flat >> 6, d = flat & 63;
        float4 v = *(const float4*)(Qg + flat);
        QsT[(d + 0) * PADF + r] = v.x;
        QsT[(d + 1) * PADF + r] = v.y;
        QsT[(d + 2) * PADF + r] = v.z;
        QsT[(d + 3) * PADF + r] = v.w;
    }
    if (tid < 64) { mrow[tid] = -INFINITY; lrow[tid] = 0.f; }

    const int ty = tid >> 3, tx = tid & 7;   // 16x8 grid
    float o[4][8];
    #pragma unroll
    for (int i = 0; i < 4; i++)
        #pragma unroll
        for (int j = 0; j < 8; j++) o[i][j] = 0.f;

    const int nkb = (q0 >> 6) + 1;
    for (int kb = 0; kb < nkb; kb++) {
        __syncthreads();   // protect K/V/S/P from previous iteration's readers
        const float* Kg = Kg0 + (size_t)kb * 64 * HD;
        const float* Vg = Vg0 + (size_t)kb * 64 * HD;
        #pragma unroll
        for (int e = 0; e < 8; e++) {
            const int flat = tid * 4 + e * 512;
            const int r = flat >> 6, d = flat & 63;
            float4 kv = *(const float4*)(Kg + flat);
            KsT[(d + 0) * PADF + r] = kv.x;
            KsT[(d + 1) * PADF + r] = kv.y;
            KsT[(d + 2) * PADF + r] = kv.z;
            KsT[(d + 3) * PADF + r] = kv.w;
            float4 vv = *(const float4*)(Vg + flat);
            *(float4*)&Vs[r * PADF + d] = vv;
        }
        __syncthreads();

        // Phase A: S[r][c] = sum_d Q[r][d] * K[c][d]
        float sa[4][8];
        #pragma unroll
        for (int i = 0; i < 4; i++)
            #pragma unroll
            for (int j = 0; j < 8; j++) sa[i][j] = 0.f;
        #pragma unroll 8
        for (int d = 0; d < 64; d++) {
            float a[4], bb[8];
            *(float4*)(a)      = *(const float4*)&QsT[d * PADF + ty * 4];
            *(float4*)(bb)     = *(const float4*)&KsT[d * PADF + tx * 8];
            *(float4*)(bb + 4) = *(const float4*)&KsT[d * PADF + tx * 8 + 4];
            #pragma unroll
            for (int i = 0; i < 4; i++)
                #pragma unroll
                for (int j = 0; j < 8; j++)
                    sa[i][j] = fmaf(a[i], bb[j], sa[i][j]);
        }
        #pragma unroll
        for (int i = 0; i < 4; i++) {
            float4 r4;
            r4.x = sa[i][0]; r4.y = sa[i][1]; r4.z = sa[i][2]; r4.w = sa[i][3];
            *(float4*)&Ss[(ty * 4 + i) * PADF + tx * 8] = r4;
            r4.x = sa[i][4]; r4.y = sa[i][5]; r4.z = sa[i][6]; r4.w = sa[i][7];
            *(float4*)&Ss[(ty * 4 + i) * PADF + tx * 8 + 4] = r4;
        }
        __syncthreads();

        // Online softmax: one thread per query row
        if (tid < 64) {
            const int r = tid;
            int lim = q0 + r - kb * 64;      // causal limit within tile
            if (lim > 63) lim = 63;
            const float mold = mrow[r];
            float mx = mold;
            for (int j = 0; j <= lim; j++)
                mx = fmaxf(mx, Ss[r * PADF + j] * 0.125f);
            const float rsc = __expf(mold - mx);
            float sum = 0.f;
            for (int j = 0; j < 64; j++) {
                const float p = (j <= lim)
                    ? __expf(Ss[r * PADF + j] * 0.125f - mx) : 0.f;
                sum += p;
                PsT[j * PADF + r] = p;
            }
            lrow[r] = lrow[r] * rsc + sum;
            mrow[r] = mx;
            resc[r] = rsc;
        }
        __syncthreads();

        // Phase B: o = o*rescale + P @ V
        float f[4];
        #pragma unroll
        for (int i = 0; i < 4; i++) f[i] = resc[ty * 4 + i];
        #pragma unroll
        for (int i = 0; i < 4; i++)
            #pragma unroll
            for (int j = 0; j < 8; j++) o[i][j] *= f[i];
        #pragma unroll 8
        for (int j = 0; j < 64; j++) {
            float p[4], vv[8];
            *(float4*)(p)      = *(const float4*)&PsT[j * PADF + ty * 4];
            *(float4*)(vv)     = *(const float4*)&Vs[j * PADF + tx * 8];
            *(float4*)(vv + 4) = *(const float4*)&Vs[j * PADF + tx * 8 + 4];
            #pragma unroll
            for (int i = 0; i < 4; i++)
                #pragma unroll
                for (int jj = 0; jj < 8; jj++)
                    o[i][jj] = fmaf(p[i], vv[jj], o[i][jj]);
        }
    }

    // Normalize and store to g_attn in [B, S, H*hd] layout
    const int b = bh >> 4, h = bh & 15;
    #pragma unroll
    for (int i = 0; i < 4; i++) {
        const int r = ty * 4 + i;
        const float inv = 1.f / lrow[r];
        float* op = g_attn + ((size_t)(b * SLEN + q0 + r)) * DM + h * HD + tx * 8;
        float4 r4;
        r4.x = o[i][0] * inv; r4.y = o[i][1] * inv;
        r4.z = o[i][2] * inv; r4.w = o[i][3] * inv;
        *(float4*)(op) = r4;
        r4.x = o[i][4] * inv; r4.y = o[i][5] * inv;
        r4.z = o[i][6] * inv; r4.w = o[i][7] * inv;
        *(float4*)(op + 4) = r4;
    }
}

// ---------------------------------------------------------------------------
// GEMM 2: out = g_attn[4096,1024] @ W_out[1024,1024]
// ---------------------------------------------------------------------------
__global__ __launch_bounds__(256) void proj_gemm_kernel(
    const float* __restrict__ W, float* __restrict__ out)
{
    __shared__ float As[8][128];
    __shared__ float Bs[8][128];
    const int tid  = threadIdx.x;
    const int row0 = blockIdx.y * 128;
    const int col0 = blockIdx.x * 128;
    const int ty = tid >> 4, tx = tid & 15;
    const int ar  = tid >> 1, akk = (tid & 1) * 4;
    const int bkk = tid >> 5, bc  = (tid & 31) * 4;

    float acc[8][8];
    #pragma unroll
    for (int i = 0; i < 8; i++)
        #pragma unroll
        for (int j = 0; j < 8; j++) acc[i][j] = 0.f;

    const float* Ap = g_attn + (size_t)(row0 + ar) * DM + akk;

    for (int k0 = 0; k0 < DM; k0 += 8) {
        float4 av = *(const float4*)(Ap + k0);
        float4 bv = *(const float4*)(W + (size_t)(k0 + bkk) * DM + col0 + bc);
        __syncthreads();
        As[akk + 0][ar] = av.x; As[akk + 1][ar] = av.y;
        As[akk + 2][ar] = av.z; As[akk + 3][ar] = av.w;
        *(float4*)&Bs[bkk][bc] = bv;
        __syncthreads();
        #pragma unroll
        for (int kk = 0; kk < 8; kk++) {
            float a[8], bb[8];
            *(float4*)(a)      = *(const float4*)&As[kk][ty * 8];
            *(float4*)(a + 4)  = *(const float4*)&As[kk][ty * 8 + 4];
            *(float4*)(bb)     = *(const float4*)&Bs[kk][tx * 8];
            *(float4*)(bb + 4) = *(const float4*)&Bs[kk][tx * 8 + 4];
            #pragma unroll
            for (int i = 0; i < 8; i++)
                #pragma unroll
                for (int j = 0; j < 8; j++)
                    acc[i][j] = fmaf(a[i], bb[j], acc[i][j]);
        }
    }

    const int gc = col0 + tx * 8;
    #pragma unroll
    for (int i = 0; i < 8; i++) {
        const int grow = row0 + ty * 8 + i;
        float* op = out + (size_t)grow * DM + gc;
        float4 r4;
        r4.x = acc[i][0]; r4.y = acc[i][1]; r4.z = acc[i][2]; r4.w = acc[i][3];
        *(float4*)(op) = r4;
        r4.x = acc[i][4]; r4.y = acc[i][5]; r4.z = acc[i][6]; r4.w = acc[i][7];
        *(float4*)(op + 4) = r4;
    }
}

// ---------------------------------------------------------------------------
extern "C" void kernel_launch(void* const* d_in, const int* in_sizes, int n_in,
                              void* d_out, int out_size)
{
    const float* x    = (const float*)d_in[0];
    const float* rc   = (const float*)d_in[1];
    const float* rs   = (const float*)d_in[2];
    const float* Wqkv = (const float*)d_in[3];
    const float* Wout = (const float*)d_in[4];
    float* out = (float*)d_out;

    const size_t shmem = (5 * 64 * PADF + 3 * 64) * sizeof(float);  // ~87.8 KB
    cudaFuncSetAttribute(flash_kernel,
                         cudaFuncAttributeMaxDynamicSharedMemorySize,
                         (int)shmem);

    qkv_gemm_kernel<<<dim3(24, 32), 256>>>(x, Wqkv, rc, rs);
    flash_kernel<<<dim3(SLEN / 64, BATCH * NHEAD), 128, shmem>>>();
    proj_gemm_kernel<<<dim3(8, 32), 256>>>(Wout, out);
}

// round 3
// speedup vs baseline: 1.3967x; 1.3967x over previous
#include <cuda_runtime.h>
#include <cuda_bf16.h>
#include <math.h>
#include <stdint.h>

#define SLEN 2048
#define DM   1024
#define NHEAD 16
#define HD   64
#define BATCH 2
#define NROWS (BATCH*SLEN)   // 4096
#define PADF 68              // padded row stride (floats) for flash smem tiles

// ---------------- scratch (device globals; no allocation allowed) ----------
__device__ float g_q[(size_t)BATCH*NHEAD*SLEN*HD];
__device__ float g_k[(size_t)BATCH*NHEAD*SLEN*HD];
__device__ float g_v[(size_t)BATCH*NHEAD*SLEN*HD];
__device__ float g_attn[(size_t)NROWS*DM];

__device__ __nv_bfloat16 g_xhi[(size_t)NROWS*DM];
__device__ __nv_bfloat16 g_xlo[(size_t)NROWS*DM];
__device__ __nv_bfloat16 g_ahi[(size_t)NROWS*DM];
__device__ __nv_bfloat16 g_alo[(size_t)NROWS*DM];
__device__ __nv_bfloat16 g_wqh[(size_t)3*DM*DM];   // W_qkv^T [3072,1024]
__device__ __nv_bfloat16 g_wql[(size_t)3*DM*DM];
__device__ __nv_bfloat16 g_woh[(size_t)DM*DM];     // W_out^T [1024,1024]
__device__ __nv_bfloat16 g_wol[(size_t)DM*DM];

// ---------------- baseline-PTX helpers (no 'a'-suffix features) -------------
__device__ __forceinline__ uint32_t smem_u32(const void* p) {
    uint32_t a;
    asm("{ .reg .u64 t; cvta.to.shared.u64 t, %1; cvt.u32.u64 %0, t; }"
        : "=r"(a) : "l"(p));
    return a;
}
__device__ __forceinline__ void cp16(uint32_t s, const void* g) {
    asm volatile("cp.async.cg.shared.global [%0], [%1], 16;"
                 :: "r"(s), "l"(g) : "memory");
}
#define CP_COMMIT() asm volatile("cp.async.commit_group;" ::: "memory")
#define CP_WAIT1()  asm volatile("cp.async.wait_group 1;" ::: "memory")

__device__ __forceinline__ void ldsm4(uint32_t* r, uint32_t addr) {
    asm volatile("ldmatrix.sync.aligned.m8n8.x4.shared.b16 {%0,%1,%2,%3}, [%4];"
        : "=r"(r[0]), "=r"(r[1]), "=r"(r[2]), "=r"(r[3]) : "r"(addr));
}
__device__ __forceinline__ void mma_bf16(float* d, const uint32_t* a,
                                         const uint32_t* b) {
    asm volatile("mma.sync.aligned.m16n8k16.row.col.f32.bf16.bf16.f32 "
        "{%0,%1,%2,%3}, {%4,%5,%6,%7}, {%8,%9}, {%0,%1,%2,%3};"
        : "+f"(d[0]), "+f"(d[1]), "+f"(d[2]), "+f"(d[3])
        : "r"(a[0]), "r"(a[1]), "r"(a[2]), "r"(a[3]), "r"(b[0]), "r"(b[1]));
}

// ---------------------------------------------------------------------------
// Convert fp32 -> (bf16 hi, bf16 lo)
// ---------------------------------------------------------------------------
__global__ __launch_bounds__(256) void conv_split_kernel(
    const float* __restrict__ src, __nv_bfloat16* __restrict__ hi,
    __nv_bfloat16* __restrict__ lo, int n)
{
    int i = (blockIdx.x * 256 + threadIdx.x) * 4;
    if (i >= n) return;
    float4 v = *(const float4*)(src + i);
    __nv_bfloat16 h0 = __float2bfloat16(v.x), h1 = __float2bfloat16(v.y);
    __nv_bfloat16 h2 = __float2bfloat16(v.z), h3 = __float2bfloat16(v.w);
    __nv_bfloat16 l0 = __float2bfloat16(v.x - __bfloat162float(h0));
    __nv_bfloat16 l1 = __float2bfloat16(v.y - __bfloat162float(h1));
    __nv_bfloat16 l2 = __float2bfloat16(v.z - __bfloat162float(h2));
    __nv_bfloat16 l3 = __float2bfloat16(v.w - __bfloat162float(h3));
    __nv_bfloat162* hp = (__nv_bfloat162*)(hi + i);
    __nv_bfloat162* lp = (__nv_bfloat162*)(lo + i);
    hp[0] = __nv_bfloat162(h0, h1); hp[1] = __nv_bfloat162(h2, h3);
    lp[0] = __nv_bfloat162(l0, l1); lp[1] = __nv_bfloat162(l2, l3);
}

// ---------------------------------------------------------------------------
// Transpose + split: W[1024, N] fp32 -> Wt_hi/lo [N, 1024] bf16
// ---------------------------------------------------------------------------
__global__ __launch_bounds__(256) void conv_wt_kernel(
    const float* __restrict__ W, __nv_bfloat16* __restrict__ hi,
    __nv_bfloat16* __restrict__ lo, int N)
{
    __shared__ float t[32][33];
    const int n0 = blockIdx.x * 32, k0 = blockIdx.y * 32;
    const int tx = threadIdx.x & 31, ty = threadIdx.x >> 5;
    #pragma unroll
    for (int i = 0; i < 4; i++)
        t[ty + i * 8][tx] = W[(size_t)(k0 + ty + i * 8) * N + n0 + tx];
    __syncthreads();
    #pragma unroll
    for (int i = 0; i < 4; i++) {
        const int n = n0 + ty + i * 8;
        const float v = t[tx][ty + i * 8];
        __nv_bfloat16 h = __float2bfloat16(v);
        hi[(size_t)n * DM + k0 + tx] = h;
        lo[(size_t)n * DM + k0 + tx] = __float2bfloat16(v - __bfloat162float(h));
    }
}

// ---------------------------------------------------------------------------
// HMMA bf16-split GEMM: D[M,N] = A[M,1024] * B[N,1024]^T, 128x128 CTA tile,
// 8 warps (4m x 2n), warp tile 32x64, mma.sync m16n8k16, K-chunk 32,
// cp.async double-buffered smem (80B row stride -> conflict-free ldmatrix).
// DO_QKV: fused RoPE + scatter epilogue to g_q/g_k/g_v. Else: store to outp.
// ---------------------------------------------------------------------------
template<int DO_QKV>
__global__ __launch_bounds__(256) void hmma_gemm_kernel(
    const __nv_bfloat16* __restrict__ Ahi, const __nv_bfloat16* __restrict__ Alo,
    const __nv_bfloat16* __restrict__ Bhi, const __nv_bfloat16* __restrict__ Blo,
    const float* __restrict__ rc, const float* __restrict__ rs,
    float* __restrict__ outp)
{
    extern __shared__ char smem[];
    const uint32_t sb = smem_u32(smem);
    const int tid = threadIdx.x, lane = tid & 31, wid = tid >> 5;
    const int wm = wid >> 1, wn = wid & 1;
    const int row0 = blockIdx.y * 128, col0 = blockIdx.x * 128;

    float acc[2][8][4];
    #pragma unroll
    for (int m = 0; m < 2; m++)
        #pragma unroll
        for (int n = 0; n < 8; n++)
            #pragma unroll
            for (int q = 0; q < 4; q++) acc[m][n][q] = 0.f;

    // loader: thread -> (row, k-half); 80B smem row stride; 40960B per buffer
    const int lrow = tid >> 1, kh = tid & 1;
    const __nv_bfloat16* ga[4];
    ga[0] = Ahi + (size_t)(row0 + lrow) * DM;
    ga[1] = Alo + (size_t)(row0 + lrow) * DM;
    ga[2] = Bhi + (size_t)(col0 + lrow) * DM;
    ga[3] = Blo + (size_t)(col0 + lrow) * DM;

    auto issue = [&](int c, int bi) {
        const int k0 = c * 32;
        const uint32_t buf = sb + bi * 40960;
        #pragma unroll
        for (int a = 0; a < 4; a++) {
            const __nv_bfloat16* gp = ga[a] + k0 + kh * 16;
            const uint32_t so = buf + a * 10240 + lrow * 80 + kh * 32;
            cp16(so,      gp);
            cp16(so + 16, gp + 8);
        }
    };

    issue(0, 0); CP_COMMIT();
    issue(1, 1); CP_COMMIT();

    for (int c = 0; c < 32; c++) {
        CP_WAIT1();
        __syncthreads();
        const uint32_t buf = sb + (c & 1) * 40960;
        #pragma unroll
        for (int ks = 0; ks < 2; ks++) {
            const int c0 = ks * 2;
            uint32_t ah[2][4], al[2][4], bh[16], bl[16];
            const int arow = wm * 32 + (lane & 15);
            const int ac = c0 + (lane >> 4);
            #pragma unroll
            for (int mt = 0; mt < 2; mt++) {
                ldsm4(ah[mt], buf +         (arow + mt * 16) * 80 + ac * 16);
                ldsm4(al[mt], buf + 10240 + (arow + mt * 16) * 80 + ac * 16);
            }
            const int brow = wn * 64 + (lane & 7) + ((lane >> 4) << 3);
            const int bc = c0 + ((lane >> 3) & 1);
            #pragma unroll
            for (int nf2 = 0; nf2 < 4; nf2++) {
                ldsm4(&bh[nf2 * 4], buf + 20480 + (brow + nf2 * 16) * 80 + bc * 16);
                ldsm4(&bl[nf2 * 4], buf + 30720 + (brow + nf2 * 16) * 80 + bc * 16);
            }
            #pragma unroll
            for (int mt = 0; mt < 2; mt++)
                #pragma unroll
                for (int nf = 0; nf < 8; nf++) {
                    mma_bf16(acc[mt][nf], ah[mt], &bh[nf * 2]);
                    mma_bf16(acc[mt][nf], ah[mt], &bl[nf * 2]);
                    mma_bf16(acc[mt][nf], al[mt], &bh[nf * 2]);
                }
        }
        __syncthreads();
        if (c + 2 < 32) { issue(c + 2, c & 1); CP_COMMIT(); }
        else            { CP_COMMIT(); }   // empty group keeps wait_group bookkeeping
    }

    // ---------------- epilogue ----------------
    const int l4 = lane >> 2, l2 = (lane & 3) * 2;
    if (DO_QKV) {
        const int part = col0 >> 10;                 // 0=q, 1=k, 2=v
        const int head = (((col0 & 1023) >> 6) + wn);
        float* dst = (part == 0) ? g_q : (part == 1) ? g_k : g_v;
        #pragma unroll
        for (int mt = 0; mt < 2; mt++) {
            #pragma unroll
            for (int rr = 0; rr < 2; rr++) {
                const int grow = row0 + wm * 32 + mt * 16 + l4 + rr * 8;
                const int b = grow >> 11, s = grow & 2047;
                float* obase = dst + ((size_t)(b * NHEAD + head) * SLEN + s) * HD;
                const float* rcp = rc + s * 32;
                const float* rsp = rs + s * 32;
                #pragma unroll
                for (int nf = 0; nf < 8; nf++) {
                    const int d = nf * 8 + l2;
                    const float v1 = acc[mt][nf][rr * 2 + 0];
                    const float v2 = acc[mt][nf][rr * 2 + 1];
                    float2 o;
                    if (part < 2) {
                        const int pi = d >> 1;
                        const float cth = rcp[pi], sth = rsp[pi];
                        o.x = v1 * cth - v2 * sth;
                        o.y = v1 * sth + v2 * cth;
                    } else {
                        o.x = v1; o.y = v2;
                    }
                    *(float2*)(obase + d) = o;
                }
            }
        }
    } else {
        #pragma unroll
        for (int mt = 0; mt < 2; mt++) {
            #pragma unroll
            for (int rr = 0; rr < 2; rr++) {
                const int grow = row0 + wm * 32 + mt * 16 + l4 + rr * 8;
                float* op = outp + (size_t)grow * DM + col0 + wn * 64 + l2;
                #pragma unroll
                for (int nf = 0; nf < 8; nf++) {
                    float2 o;
                    o.x = acc[mt][nf][rr * 2 + 0];
                    o.y = acc[mt][nf][rr * 2 + 1];
                    *(float2*)(op + nf * 8) = o;
                }
            }
        }
    }
}

// ---------------------------------------------------------------------------
// FlashAttention-2 style causal attention, fp32 (round-1 version, unchanged).
// ---------------------------------------------------------------------------
__global__ __launch_bounds__(128) void flash_kernel()
{
    extern __shared__ float sm[];
    float* QsT  = sm;                 // [d][r] 64x68
    float* KsT  = QsT + 64 * PADF;    // [d][c]
    float* Vs   = KsT + 64 * PADF;    // [j][d]
    float* Ss   = Vs  + 64 * PADF;    // [r][j]
    float* PsT  = Ss  + 64 * PADF;    // [j][r]
    float* mrow = PsT + 64 * PADF;    // [64]
    float* lrow = mrow + 64;          // [64]
    float* resc = lrow + 64;          // [64]

    const int tid = threadIdx.x;
    const int q0  = blockIdx.x * 64;
    const int bh  = blockIdx.y;

    const float* Qg  = g_q + ((size_t)bh * SLEN + q0) * HD;
    const float* Kg0 = g_k + (size_t)bh * SLEN * HD;
    const float* Vg0 = g_v + (size_t)bh * SLEN * HD;

    #pragma unroll
    for (int e = 0; e < 8; e++) {
        const int flat = tid * 4 + e * 512;
        const int r = flat >> 6, d = flat & 63;
        float4 v = *(const float4*)(Qg + flat);
        QsT[(d + 0) * PADF + r] = v.x;
        QsT[(d + 1) * PADF + r] = v.y;
        QsT[(d + 2) * PADF + r] = v.z;
        QsT[(d + 3) * PADF + r] = v.w;
    }
    if (tid < 64) { mrow[tid] = -INFINITY; lrow[tid] = 0.f; }

    const int ty = tid >> 3, tx = tid & 7;   // 16x8 grid
    float o[4][8];
    #pragma unroll
    for (int i = 0; i < 4; i++)
        #pragma unroll
        for (int j = 0; j < 8; j++) o[i][j] = 0.f;

    const int nkb = (q0 >> 6) + 1;
    for (int kb = 0; kb < nkb; kb++) {
        __syncthreads();
        const float* Kg = Kg0 + (size_t)kb * 64 * HD;
        const float* Vg = Vg0 + (size_t)kb * 64 * HD;
        #pragma unroll
        for (int e = 0; e < 8; e++) {
            const int flat = tid * 4 + e * 512;
            const int r = flat >> 6, d = flat & 63;
            float4 kv = *(const float4*)(Kg + flat);
            KsT[(d + 0) * PADF + r] = kv.x;
            KsT[(d + 1) * PADF + r] = kv.y;
            KsT[(d + 2) * PADF + r] = kv.z;
            KsT[(d + 3) * PADF + r] = kv.w;
            float4 vv = *(const float4*)(Vg + flat);
            *(float4*)&Vs[r * PADF + d] = vv;
        }
        __syncthreads();

        float sa[4][8];
        #pragma unroll
        for (int i = 0; i < 4; i++)
            #pragma unroll
            for (int j = 0; j < 8; j++) sa[i][j] = 0.f;
        #pragma unroll 8
        for (int d = 0; d < 64; d++) {
            float a[4], bb[8];
            *(float4*)(a)      = *(const float4*)&QsT[d * PADF + ty * 4];
            *(float4*)(bb)     = *(const float4*)&KsT[d * PADF + tx * 8];
            *(float4*)(bb + 4) = *(const float4*)&KsT[d * PADF + tx * 8 + 4];
            #pragma unroll
            for (int i = 0; i < 4; i++)
                #pragma unroll
                for (int j = 0; j < 8; j++)
                    sa[i][j] = fmaf(a[i], bb[j], sa[i][j]);
        }
        #pragma unroll
        for (int i = 0; i < 4; i++) {
            float4 r4;
            r4.x = sa[i][0]; r4.y = sa[i][1]; r4.z = sa[i][2]; r4.w = sa[i][3];
            *(float4*)&Ss[(ty * 4 + i) * PADF + tx * 8] = r4;
            r4.x = sa[i][4]; r4.y = sa[i][5]; r4.z = sa[i][6]; r4.w = sa[i][7];
            *(float4*)&Ss[(ty * 4 + i) * PADF + tx * 8 + 4] = r4;
        }
        __syncthreads();

        if (tid < 64) {
            const int r = tid;
            int lim = q0 + r - kb * 64;
            if (lim > 63) lim = 63;
            const float mold = mrow[r];
            float mx = mold;
            for (int j = 0; j <= lim; j++)
                mx = fmaxf(mx, Ss[r * PADF + j] * 0.125f);
            const float rsc = __expf(mold - mx);
            float sum = 0.f;
            for (int j = 0; j < 64; j++) {
                const float p = (j <= lim)
                    ? __expf(Ss[r * PADF + j] * 0.125f - mx) : 0.f;
                sum += p;
                PsT[j * PADF + r] = p;
            }
            lrow[r] = lrow[r] * rsc + sum;
            mrow[r] = mx;
            resc[r] = rsc;
        }
        __syncthreads();

        float f[4];
        #pragma unroll
        for (int i = 0; i < 4; i++) f[i] = resc[ty * 4 + i];
        #pragma unroll
        for (int i = 0; i < 4; i++)
            #pragma unroll
            for (int j = 0; j < 8; j++) o[i][j] *= f[i];
        #pragma unroll 8
        for (int j = 0; j < 64; j++) {
            float p[4], vv[8];
            *(float4*)(p)      = *(const float4*)&PsT[j * PADF + ty * 4];
            *(float4*)(vv)     = *(const float4*)&Vs[j * PADF + tx * 8];
            *(float4*)(vv + 4) = *(const float4*)&Vs[j * PADF + tx * 8 + 4];
            #pragma unroll
            for (int i = 0; i < 4; i++)
                #pragma unroll
                for (int jj = 0; jj < 8; jj++)
                    o[i][jj] = fmaf(p[i], vv[jj], o[i][jj]);
        }
    }

    const int b = bh >> 4, h = bh & 15;
    #pragma unroll
    for (int i = 0; i < 4; i++) {
        const int r = ty * 4 + i;
        const float inv = 1.f / lrow[r];
        float* op = g_attn + ((size_t)(b * SLEN + q0 + r)) * DM + h * HD + tx * 8;
        float4 r4;
        r4.x = o[i][0] * inv; r4.y = o[i][1] * inv;
        r4.z = o[i][2] * inv; r4.w = o[i][3] * inv;
        *(float4*)(op) = r4;
        r4.x = o[i][4] * inv; r4.y = o[i][5] * inv;
        r4.z = o[i][6] * inv; r4.w = o[i][7] * inv;
        *(float4*)(op + 4) = r4;
    }
}

// ---------------------------------------------------------------------------
extern "C" void kernel_launch(void* const* d_in, const int* in_sizes, int n_in,
                              void* d_out, int out_size)
{
    const float* x    = (const float*)d_in[0];
    const float* rc   = (const float*)d_in[1];
    const float* rs   = (const float*)d_in[2];
    const float* Wqkv = (const float*)d_in[3];
    const float* Wout = (const float*)d_in[4];
    float* out = (float*)d_out;

    const size_t flash_sh = (5 * 64 * PADF + 3 * 64) * sizeof(float);
    const size_t mma_sh = 81920;
    cudaFuncSetAttribute(flash_kernel,
        cudaFuncAttributeMaxDynamicSharedMemorySize, (int)flash_sh);
    cudaFuncSetAttribute(hmma_gemm_kernel<1>,
        cudaFuncAttributeMaxDynamicSharedMemorySize, (int)mma_sh);
    cudaFuncSetAttribute(hmma_gemm_kernel<0>,
        cudaFuncAttributeMaxDynamicSharedMemorySize, (int)mma_sh);

    __nv_bfloat16 *xhi, *xlo, *ahi, *alo, *wqh, *wql, *woh, *wol;
    float *attn;
    cudaGetSymbolAddress((void**)&xhi, g_xhi);
    cudaGetSymbolAddress((void**)&xlo, g_xlo);
    cudaGetSymbolAddress((void**)&ahi, g_ahi);
    cudaGetSymbolAddress((void**)&alo, g_alo);
    cudaGetSymbolAddress((void**)&wqh, g_wqh);
    cudaGetSymbolAddress((void**)&wql, g_wql);
    cudaGetSymbolAddress((void**)&woh, g_woh);
    cudaGetSymbolAddress((void**)&wol, g_wol);
    cudaGetSymbolAddress((void**)&attn, g_attn);

    // 1. splits / transposes
    conv_split_kernel<<<(NROWS * DM) / 1024, 256>>>(x, xhi, xlo, NROWS * DM);
    conv_wt_kernel<<<dim3(96, 32), 256>>>(Wqkv, wqh, wql, 3 * DM);
    conv_wt_kernel<<<dim3(32, 32), 256>>>(Wout, woh, wol, DM);

    // 2. QKV GEMM (HMMA) + fused RoPE scatter
    hmma_gemm_kernel<1><<<dim3(24, 32), 256, mma_sh>>>(
        xhi, xlo, wqh, wql, rc, rs, nullptr);

    // 3. flash attention (fp32)
    flash_kernel<<<dim3(SLEN / 64, BATCH * NHEAD), 128, flash_sh>>>();

    // 4. split attn output, out-projection GEMM (HMMA)
    conv_split_kernel<<<(NROWS * DM) / 1024, 256>>>(attn, ahi, alo, NROWS * DM);
    hmma_gemm_kernel<0><<<dim3(8, 32), 256, mma_sh>>>(
        ahi, alo, woh, wol, nullptr, nullptr, out);
}

// round 4
// speedup vs baseline: 3.0200x; 2.1623x over previous
#include <cuda_runtime.h>
#include <cuda_bf16.h>
#include <math.h>
#include <stdint.h>

#define SLEN 2048
#define DM   1024
#define NHEAD 16
#define HD   64
#define BATCH 2
#define NROWS (BATCH*SLEN)   // 4096

// ---------------- scratch (device globals; no allocation allowed) ----------
__device__ __nv_bfloat16 g_xhi[(size_t)NROWS*DM];
__device__ __nv_bfloat16 g_xlo[(size_t)NROWS*DM];
__device__ __nv_bfloat16 g_ahi[(size_t)NROWS*DM];
__device__ __nv_bfloat16 g_alo[(size_t)NROWS*DM];
__device__ __nv_bfloat16 g_wqh[(size_t)3*DM*DM];   // W_qkv^T [3072,1024]
__device__ __nv_bfloat16 g_wql[(size_t)3*DM*DM];
__device__ __nv_bfloat16 g_woh[(size_t)DM*DM];     // W_out^T [1024,1024]
__device__ __nv_bfloat16 g_wol[(size_t)DM*DM];
// q/k/v split bf16, layout [B*H][S][64]
__device__ __nv_bfloat16 g_qhi[(size_t)BATCH*NHEAD*SLEN*HD];
__device__ __nv_bfloat16 g_qlo[(size_t)BATCH*NHEAD*SLEN*HD];
__device__ __nv_bfloat16 g_khi[(size_t)BATCH*NHEAD*SLEN*HD];
__device__ __nv_bfloat16 g_klo[(size_t)BATCH*NHEAD*SLEN*HD];
__device__ __nv_bfloat16 g_vhi[(size_t)BATCH*NHEAD*SLEN*HD];
__device__ __nv_bfloat16 g_vlo[(size_t)BATCH*NHEAD*SLEN*HD];

// ---------------- baseline-PTX helpers -------------------------------------
__device__ __forceinline__ uint32_t smem_u32(const void* p) {
    uint32_t a;
    asm("{ .reg .u64 t; cvta.to.shared.u64 t, %1; cvt.u32.u64 %0, t; }"
        : "=r"(a) : "l"(p));
    return a;
}
__device__ __forceinline__ void cp16(uint32_t s, const void* g) {
    asm volatile("cp.async.cg.shared.global [%0], [%1], 16;"
                 :: "r"(s), "l"(g) : "memory");
}
#define CP_COMMIT() asm volatile("cp.async.commit_group;" ::: "memory")
#define CP_WAIT1()  asm volatile("cp.async.wait_group 1;" ::: "memory")
#define CP_WAIT0()  asm volatile("cp.async.wait_group 0;" ::: "memory")

__device__ __forceinline__ void ldsm4(uint32_t* r, uint32_t addr) {
    asm volatile("ldmatrix.sync.aligned.m8n8.x4.shared.b16 {%0,%1,%2,%3}, [%4];"
        : "=r"(r[0]), "=r"(r[1]), "=r"(r[2]), "=r"(r[3]) : "r"(addr));
}
__device__ __forceinline__ void ldsm4t(uint32_t* r, uint32_t addr) {
    asm volatile("ldmatrix.sync.aligned.m8n8.x4.trans.shared.b16 {%0,%1,%2,%3}, [%4];"
        : "=r"(r[0]), "=r"(r[1]), "=r"(r[2]), "=r"(r[3]) : "r"(addr));
}
__device__ __forceinline__ void mma_bf16(float* d, const uint32_t* a,
                                         const uint32_t* b) {
    asm volatile("mma.sync.aligned.m16n8k16.row.col.f32.bf16.bf16.f32 "
        "{%0,%1,%2,%3}, {%4,%5,%6,%7}, {%8,%9}, {%0,%1,%2,%3};"
        : "+f"(d[0]), "+f"(d[1]), "+f"(d[2]), "+f"(d[3])
        : "r"(a[0]), "r"(a[1]), "r"(a[2]), "r"(a[3]), "r"(b[0]), "r"(b[1]));
}
// pack two fp32 -> bf16x2 (lo in low half)
__device__ __forceinline__ uint32_t packbf(float lo, float hi) {
    uint32_t d;
    asm("cvt.rn.bf16x2.f32 %0, %1, %2;" : "=r"(d) : "f"(hi), "f"(lo));
    return d;
}
__device__ __forceinline__ float bflo(uint32_t u) { return __int_as_float(u << 16); }
__device__ __forceinline__ float bfhi(uint32_t u) { return __int_as_float(u & 0xFFFF0000u); }

// exp2 via FFMA poly (no MUFU). z expected <= 0; clamped at -40.
__device__ __forceinline__ float fast_exp2(float z) {
    z = fmaxf(z, -40.f);
    const float km = z + 12582912.f;          // round-to-nearest int
    const int   ki = __float_as_int(km) - 0x4B400000;   // = round(z)
    const float f  = z - (km - 12582912.f);   // frac in [-0.5, 0.5]
    float p = 0.0013333558f;
    p = fmaf(p, f, 0.0096181815f);
    p = fmaf(p, f, 0.0555041087f);
    p = fmaf(p, f, 0.2402265069f);
    p = fmaf(p, f, 0.6931471806f);
    p = fmaf(p, f, 1.0f);
    return p * __int_as_float((ki + 127) << 23);
}

#define SCQ 0.18033688011112042f   // hd^-0.5 * log2(e), folded into Q

// ---------------------------------------------------------------------------
// Convert fp32 -> (bf16 hi, bf16 lo)
// ---------------------------------------------------------------------------
__global__ __launch_bounds__(256) void conv_split_kernel(
    const float* __restrict__ src, __nv_bfloat16* __restrict__ hi,
    __nv_bfloat16* __restrict__ lo, int n)
{
    int i = (blockIdx.x * 256 + threadIdx.x) * 4;
    if (i >= n) return;
    float4 v = *(const float4*)(src + i);
    uint32_t h0 = packbf(v.x, v.y), h1 = packbf(v.z, v.w);
    uint32_t l0 = packbf(v.x - bflo(h0), v.y - bfhi(h0));
    uint32_t l1 = packbf(v.z - bflo(h1), v.w - bfhi(h1));
    uint2* hp = (uint2*)(hi + i); *hp = make_uint2(h0, h1);
    uint2* lp = (uint2*)(lo + i); *lp = make_uint2(l0, l1);
}

// ---------------------------------------------------------------------------
// Transpose + split: W[1024, N] fp32 -> Wt_hi/lo [N, 1024] bf16
// ---------------------------------------------------------------------------
__global__ __launch_bounds__(256) void conv_wt_kernel(
    const float* __restrict__ W, __nv_bfloat16* __restrict__ hi,
    __nv_bfloat16* __restrict__ lo, int N)
{
    __shared__ float t[32][33];
    const int n0 = blockIdx.x * 32, k0 = blockIdx.y * 32;
    const int tx = threadIdx.x & 31, ty = threadIdx.x >> 5;
    #pragma unroll
    for (int i = 0; i < 4; i++)
        t[ty + i * 8][tx] = W[(size_t)(k0 + ty + i * 8) * N + n0 + tx];
    __syncthreads();
    #pragma unroll
    for (int i = 0; i < 4; i++) {
        const int n = n0 + ty + i * 8;
        const float v = t[tx][ty + i * 8];
        __nv_bfloat16 h = __float2bfloat16(v);
        hi[(size_t)n * DM + k0 + tx] = h;
        lo[(size_t)n * DM + k0 + tx] = __float2bfloat16(v - __bfloat162float(h));
    }
}

// ---------------------------------------------------------------------------
// HMMA bf16-split GEMM (as round 3): D[M,N] = A[M,1024] * B[N,1024]^T.
// DO_QKV: fused RoPE + bf16 hi/lo split scatter to g_q/k/v (Q pre-scaled).
// ---------------------------------------------------------------------------
template<int DO_QKV>
__global__ __launch_bounds__(256) void hmma_gemm_kernel(
    const __nv_bfloat16* __restrict__ Ahi, const __nv_bfloat16* __restrict__ Alo,
    const __nv_bfloat16* __restrict__ Bhi, const __nv_bfloat16* __restrict__ Blo,
    const float* __restrict__ rc, const float* __restrict__ rs,
    float* __restrict__ outp)
{
    extern __shared__ char smem[];
    const uint32_t sb = smem_u32(smem);
    const int tid = threadIdx.x, lane = tid & 31, wid = tid >> 5;
    const int wm = wid >> 1, wn = wid & 1;
    const int row0 = blockIdx.y * 128, col0 = blockIdx.x * 128;

    float acc[2][8][4];
    #pragma unroll
    for (int m = 0; m < 2; m++)
        #pragma unroll
        for (int n = 0; n < 8; n++)
            #pragma unroll
            for (int q = 0; q < 4; q++) acc[m][n][q] = 0.f;

    const int lrow = tid >> 1, kh = tid & 1;
    const __nv_bfloat16* ga[4];
    ga[0] = Ahi + (size_t)(row0 + lrow) * DM;
    ga[1] = Alo + (size_t)(row0 + lrow) * DM;
    ga[2] = Bhi + (size_t)(col0 + lrow) * DM;
    ga[3] = Blo + (size_t)(col0 + lrow) * DM;

    auto issue = [&](int c, int bi) {
        const int k0 = c * 32;
        const uint32_t buf = sb + bi * 40960;
        #pragma unroll
        for (int a = 0; a < 4; a++) {
            const __nv_bfloat16* gp = ga[a] + k0 + kh * 16;
            const uint32_t so = buf + a * 10240 + lrow * 80 + kh * 32;
            cp16(so,      gp);
            cp16(so + 16, gp + 8);
        }
    };

    issue(0, 0); CP_COMMIT();
    issue(1, 1); CP_COMMIT();

    for (int c = 0; c < 32; c++) {
        CP_WAIT1();
        __syncthreads();
        const uint32_t buf = sb + (c & 1) * 40960;
        #pragma unroll
        for (int ks = 0; ks < 2; ks++) {
            const int c0 = ks * 2;
            uint32_t ah[2][4], al[2][4], bh[16], bl[16];
            const int arow = wm * 32 + (lane & 15);
            const int ac = c0 + (lane >> 4);
            #pragma unroll
            for (int mt = 0; mt < 2; mt++) {
                ldsm4(ah[mt], buf +         (arow + mt * 16) * 80 + ac * 16);
                ldsm4(al[mt], buf + 10240 + (arow + mt * 16) * 80 + ac * 16);
            }
            const int brow = wn * 64 + (lane & 7) + ((lane >> 4) << 3);
            const int bc = c0 + ((lane >> 3) & 1);
            #pragma unroll
            for (int nf2 = 0; nf2 < 4; nf2++) {
                ldsm4(&bh[nf2 * 4], buf + 20480 + (brow + nf2 * 16) * 80 + bc * 16);
                ldsm4(&bl[nf2 * 4], buf + 30720 + (brow + nf2 * 16) * 80 + bc * 16);
            }
            #pragma unroll
            for (int mt = 0; mt < 2; mt++)
                #pragma unroll
                for (int nf = 0; nf < 8; nf++) {
                    mma_bf16(acc[mt][nf], ah[mt], &bh[nf * 2]);
                    mma_bf16(acc[mt][nf], ah[mt], &bl[nf * 2]);
                    mma_bf16(acc[mt][nf], al[mt], &bh[nf * 2]);
                }
        }
        __syncthreads();
        if (c + 2 < 32) { issue(c + 2, c & 1); CP_COMMIT(); }
        else            { CP_COMMIT(); }
    }

    // ---------------- epilogue ----------------
    const int l4 = lane >> 2, l2 = (lane & 3) * 2;
    if (DO_QKV) {
        const int part = col0 >> 10;                 // 0=q, 1=k, 2=v
        const int head = ((col0 & 1023) >> 6) + wn;
        __nv_bfloat16* dhi = (part == 0) ? g_qhi : (part == 1) ? g_khi : g_vhi;
        __nv_bfloat16* dlo = (part == 0) ? g_qlo : (part == 1) ? g_klo : g_vlo;
        #pragma unroll
        for (int mt = 0; mt < 2; mt++) {
            #pragma unroll
            for (int rr = 0; rr < 2; rr++) {
                const int grow = row0 + wm * 32 + mt * 16 + l4 + rr * 8;
                const int b = grow >> 11, s = grow & 2047;
                const size_t obase = ((size_t)(b * NHEAD + head) * SLEN + s) * HD;
                const float* rcp = rc + s * 32;
                const float* rsp = rs + s * 32;
                #pragma unroll
                for (int nf = 0; nf < 8; nf++) {
                    const int d = nf * 8 + l2;
                    const float v1 = acc[mt][nf][rr * 2 + 0];
                    const float v2 = acc[mt][nf][rr * 2 + 1];
                    float ox, oy;
                    if (part < 2) {
                        const int pi = d >> 1;
                        const float cth = rcp[pi], sth = rsp[pi];
                        ox = v1 * cth - v2 * sth;
                        oy = v1 * sth + v2 * cth;
                        if (part == 0) { ox *= SCQ; oy *= SCQ; }
                    } else {
                        ox = v1; oy = v2;
                    }
                    const uint32_t hb = packbf(ox, oy);
                    const uint32_t lb = packbf(ox - bflo(hb), oy - bfhi(hb));
                    *(uint32_t*)(dhi + obase + d) = hb;
                    *(uint32_t*)(dlo + obase + d) = lb;
                }
            }
        }
    } else {
        #pragma unroll
        for (int mt = 0; mt < 2; mt++) {
            #pragma unroll
            for (int rr = 0; rr < 2; rr++) {
                const int grow = row0 + wm * 32 + mt * 16 + l4 + rr * 8;
                float* op = outp + (size_t)grow * DM + col0 + wn * 64 + l2;
                #pragma unroll
                for (int nf = 0; nf < 8; nf++) {
                    float2 o;
                    o.x = acc[mt][nf][rr * 2 + 0];
                    o.y = acc[mt][nf][rr * 2 + 1];
                    *(float2*)(op + nf * 8) = o;
                }
            }
        }
    }
}

// ---------------------------------------------------------------------------
// HMMA FlashAttention: BM=128 queries, KN=128 keys/tile, 256 thr (8 warps,
// each warp owns 16 query rows x all 128 key cols). Split-precision bf16
// (hi/lo) for QK and PV; softmax with FFMA exp2; P stays in registers
// (C-fragment layout == A-fragment layout). Writes bf16 hi/lo to g_ahi/g_alo.
// smem: 6 tiles of 128 rows x 72 bf16 (144B stride, conflict-free ldmatrix).
// ---------------------------------------------------------------------------
#define FTILE 18432          // 128*72*2 bytes
__global__ __launch_bounds__(256) void flash_hmma_kernel()
{
    extern __shared__ char fsm[];
    const uint32_t sb = smem_u32(fsm);
    const uint32_t Qh = sb,             Ql = sb + FTILE;
    const uint32_t Kh = sb + 2 * FTILE, Kl = sb + 3 * FTILE;
    const uint32_t Vh = sb + 4 * FTILE, Vl = sb + 5 * FTILE;

    const int tid = threadIdx.x, lane = tid & 31, w = tid >> 5;
    const int qb = gridDim.x - 1 - blockIdx.x;      // long CTAs first
    const int q0 = qb * 128, bh = blockIdx.y;
    const size_t base = (size_t)bh * SLEN * HD;

    const __nv_bfloat16 *qhg = g_qhi + base + (size_t)q0 * HD;
    const __nv_bfloat16 *qlg = g_qlo + base + (size_t)q0 * HD;
    const __nv_bfloat16 *khg = g_khi + base, *klg = g_klo + base;
    const __nv_bfloat16 *vhg = g_vhi + base, *vlg = g_vlo + base;

    auto ldtile = [&](uint32_t dh, uint32_t dl,
                      const __nv_bfloat16* gh, const __nv_bfloat16* gl) {
        #pragma unroll
        for (int kk = 0; kk < 4; kk++) {
            const int c = tid + kk * 256;
            const int row = c >> 3, q8 = c & 7;
            cp16(dh + row * 144 + q8 * 16, gh + row * 64 + q8 * 8);
            cp16(dl + row * 144 + q8 * 16, gl + row * 64 + q8 * 8);
        }
    };

    ldtile(Qh, Ql, qhg, qlg);
    ldtile(Kh, Kl, khg, klg);
    CP_COMMIT();
    ldtile(Vh, Vl, vhg, vlg);
    CP_COMMIT();

    uint32_t qfh[4][4], qfl[4][4];
    float oacc[8][4];
    #pragma unroll
    for (int j = 0; j < 8; j++)
        #pragma unroll
        for (int q = 0; q < 4; q++) oacc[j][q] = 0.f;
    float m0 = -1e30f, m1 = -1e30f, l0 = 0.f, l1 = 0.f;

    const int nkb = qb + 1;
    for (int kb = 0; kb < nkb; kb++) {
        const bool lastt = (kb == nkb - 1);
        CP_WAIT1();
        __syncthreads();
        if (kb == 0) {
            #pragma unroll
            for (int ks = 0; ks < 4; ks++) {
                const uint32_t a = (uint32_t)((w * 16 + (lane & 15)) * 144
                                 + (ks * 16 + (lane >> 4) * 8) * 2);
                ldsm4(qfh[ks], Qh + a);
                ldsm4(qfl[ks], Ql + a);
            }
        }
        // ---- S = Q @ K^T (split precision) ----
        float sacc[16][4];
        #pragma unroll
        for (int j = 0; j < 16; j++)
            #pragma unroll
            for (int q = 0; q < 4; q++) sacc[j][q] = 0.f;
        #pragma unroll
        for (int ks = 0; ks < 4; ks++) {
            #pragma unroll
            for (int p = 0; p < 8; p++) {
                uint32_t kh4[4], kl4[4];
                const uint32_t a = (uint32_t)((p * 16 + (lane & 15)) * 144
                                 + (ks * 16 + (lane >> 4) * 8) * 2);
                ldsm4(kh4, Kh + a);
                ldsm4(kl4, Kl + a);
                uint32_t bh0[2] = {kh4[0], kh4[2]}, bh1[2] = {kh4[1], kh4[3]};
                uint32_t bl0[2] = {kl4[0], kl4[2]}, bl1[2] = {kl4[1], kl4[3]};
                mma_bf16(sacc[2 * p],     qfh[ks], bh0);
                mma_bf16(sacc[2 * p],     qfh[ks], bl0);
                mma_bf16(sacc[2 * p],     qfl[ks], bh0);
                mma_bf16(sacc[2 * p + 1], qfh[ks], bh1);
                mma_bf16(sacc[2 * p + 1], qfh[ks], bl1);
                mma_bf16(sacc[2 * p + 1], qfl[ks], bh1);
            }
        }
        __syncthreads();                 // all warps done reading K smem
        if (!lastt) {
            ldtile(Kh, Kl, khg + (size_t)(kb + 1) * 128 * HD,
                           klg + (size_t)(kb + 1) * 128 * HD);
            CP_COMMIT();
        }

        // ---- softmax (registers only; overlaps with K prefetch) ----
        if (lastt) {  // diagonal tile: mask col > row (tile-local, kb*128==q0)
            const int rl0 = w * 16 + (lane >> 2);
            #pragma unroll
            for (int j = 0; j < 16; j++) {
                const int c = j * 8 + (lane & 3) * 2;
                if (c     > rl0)     sacc[j][0] = -1e30f;
                if (c + 1 > rl0)     sacc[j][1] = -1e30f;
                if (c     > rl0 + 8) sacc[j][2] = -1e30f;
                if (c + 1 > rl0 + 8) sacc[j][3] = -1e30f;
            }
        }
        float rmx0 = -1e30f, rmx1 = -1e30f;
        #pragma unroll
        for (int j = 0; j < 16; j++) {
            rmx0 = fmaxf(rmx0, fmaxf(sacc[j][0], sacc[j][1]));
            rmx1 = fmaxf(rmx1, fmaxf(sacc[j][2], sacc[j][3]));
        }
        rmx0 = fmaxf(rmx0, __shfl_xor_sync(0xffffffffu, rmx0, 1));
        rmx0 = fmaxf(rmx0, __shfl_xor_sync(0xffffffffu, rmx0, 2));
        rmx1 = fmaxf(rmx1, __shfl_xor_sync(0xffffffffu, rmx1, 1));
        rmx1 = fmaxf(rmx1, __shfl_xor_sync(0xffffffffu, rmx1, 2));
        const float mn0 = fmaxf(m0, rmx0), mn1 = fmaxf(m1, rmx1);
        const float rs0 = fast_exp2(m0 - mn0), rs1 = fast_exp2(m1 - mn1);
        m0 = mn0; m1 = mn1;
        float sum0 = 0.f, sum1 = 0.f;
        #pragma unroll
        for (int j = 0; j < 16; j++) {
            sacc[j][0] = fast_exp2(sacc[j][0] - m0);
            sacc[j][1] = fast_exp2(sacc[j][1] - m0);
            sacc[j][2] = fast_exp2(sacc[j][2] - m1);
            sacc[j][3] = fast_exp2(sacc[j][3] - m1);
            sum0 += sacc[j][0] + sacc[j][1];
            sum1 += sacc[j][2] + sacc[j][3];
        }
        sum0 += __shfl_xor_sync(0xffffffffu, sum0, 1);
        sum0 += __shfl_xor_sync(0xffffffffu, sum0, 2);
        sum1 += __shfl_xor_sync(0xffffffffu, sum1, 1);
        sum1 += __shfl_xor_sync(0xffffffffu, sum1, 2);
        l0 = l0 * rs0 + sum0;
        l1 = l1 * rs1 + sum1;
        #pragma unroll
        for (int j = 0; j < 8; j++) {
            oacc[j][0] *= rs0; oacc[j][1] *= rs0;
            oacc[j][2] *= rs1; oacc[j][3] *= rs1;
        }

        // ---- O += P @ V (split precision; P from S accumulators) ----
        if (!lastt) CP_WAIT1(); else CP_WAIT0();
        __syncthreads();
        #pragma unroll
        for (int ks = 0; ks < 8; ks++) {
            const float* s0 = sacc[2 * ks];
            const float* s1 = sacc[2 * ks + 1];
            uint32_t ph[4], pl[4];
            ph[0] = packbf(s0[0], s0[1]); ph[1] = packbf(s0[2], s0[3]);
            ph[2] = packbf(s1[0], s1[1]); ph[3] = packbf(s1[2], s1[3]);
            pl[0] = packbf(s0[0] - bflo(ph[0]), s0[1] - bfhi(ph[0]));
            pl[1] = packbf(s0[2] - bflo(ph[1]), s0[3] - bfhi(ph[1]));
            pl[2] = packbf(s1[0] - bflo(ph[2]), s1[1] - bfhi(ph[2]));
            pl[3] = packbf(s1[2] - bflo(ph[3]), s1[3] - bfhi(ph[3]));
            #pragma unroll
            for (int p = 0; p < 4; p++) {
                uint32_t vh4[4], vl4[4];
                const uint32_t a = (uint32_t)((ks * 16 + (lane & 15)) * 144
                                 + (p * 16 + (lane >> 4) * 8) * 2);
                ldsm4t(vh4, Vh + a);
                ldsm4t(vl4, Vl + a);
                uint32_t bh0[2] = {vh4[0], vh4[1]}, bh1[2] = {vh4[2], vh4[3]};
                uint32_t bl0[2] = {vl4[0], vl4[1]}, bl1[2] = {vl4[2], vl4[3]};
                mma_bf16(oacc[2 * p],     ph, bh0);
                mma_bf16(oacc[2 * p],     ph, bl0);
                mma_bf16(oacc[2 * p],     pl, bh0);
                mma_bf16(oacc[2 * p + 1], ph, bh1);
                mma_bf16(oacc[2 * p + 1], ph, bl1);
                mma_bf16(oacc[2 * p + 1], pl, bh1);
            }
        }
        __syncthreads();                 // all warps done reading V smem
        if (!lastt) {
            ldtile(Vh, Vl, vhg + (size_t)(kb + 1) * 128 * HD,
                           vlg + (size_t)(kb + 1) * 128 * HD);
            CP_COMMIT();
        }
    }

    // ---- epilogue: normalize, split to bf16 hi/lo, write [B,S,D] ----
    const float inv0 = 1.f / l0, inv1 = 1.f / l1;
    const int b = bh >> 4, h = bh & 15;
    const int s0r = q0 + w * 16 + (lane >> 2);
    const size_t rowA = (size_t)(b * SLEN + s0r);
    const size_t rowB = rowA + 8;
    const int colb = h * 64 + (lane & 3) * 2;
    #pragma unroll
    for (int j = 0; j < 8; j++) {
        const int col = colb + j * 8;
        const float x0 = oacc[j][0] * inv0, x1 = oacc[j][1] * inv0;
        const float y0 = oacc[j][2] * inv1, y1 = oacc[j][3] * inv1;
        uint32_t hb = packbf(x0, x1);
        uint32_t lb = packbf(x0 - bflo(hb), x1 - bfhi(hb));
        *(uint32_t*)(g_ahi + rowA * DM + col) = hb;
        *(uint32_t*)(g_alo + rowA * DM + col) = lb;
        hb = packbf(y0, y1);
        lb = packbf(y0 - bflo(hb), y1 - bfhi(hb));
        *(uint32_t*)(g_ahi + rowB * DM + col) = hb;
        *(uint32_t*)(g_alo + rowB * DM + col) = lb;
    }
}

// ---------------------------------------------------------------------------
extern "C" void kernel_launch(void* const* d_in, const int* in_sizes, int n_in,
                              void* d_out, int out_size)
{
    const float* x    = (const float*)d_in[0];
    const float* rc   = (const float*)d_in[1];
    const float* rs   = (const float*)d_in[2];
    const float* Wqkv = (const float*)d_in[3];
    const float* Wout = (const float*)d_in[4];
    float* out = (float*)d_out;

    const size_t mma_sh   = 81920;
    const size_t flash_sh = 6 * FTILE;   // 110592
    cudaFuncSetAttribute(hmma_gemm_kernel<1>,
        cudaFuncAttributeMaxDynamicSharedMemorySize, (int)mma_sh);
    cudaFuncSetAttribute(hmma_gemm_kernel<0>,
        cudaFuncAttributeMaxDynamicSharedMemorySize, (int)mma_sh);
    cudaFuncSetAttribute(flash_hmma_kernel,
        cudaFuncAttributeMaxDynamicSharedMemorySize, (int)flash_sh);

    __nv_bfloat16 *xhi, *xlo, *ahi, *alo, *wqh, *wql, *woh, *wol;
    cudaGetSymbolAddress((void**)&xhi, g_xhi);
    cudaGetSymbolAddress((void**)&xlo, g_xlo);
    cudaGetSymbolAddress((void**)&ahi, g_ahi);
    cudaGetSymbolAddress((void**)&alo, g_alo);
    cudaGetSymbolAddress((void**)&wqh, g_wqh);
    cudaGetSymbolAddress((void**)&wql, g_wql);
    cudaGetSymbolAddress((void**)&woh, g_woh);
    cudaGetSymbolAddress((void**)&wol, g_wol);

    // 1. splits / transposes
    conv_split_kernel<<<(NROWS * DM) / 1024, 256>>>(x, xhi, xlo, NROWS * DM);
    conv_wt_kernel<<<dim3(96, 32), 256>>>(Wqkv, wqh, wql, 3 * DM);
    conv_wt_kernel<<<dim3(32, 32), 256>>>(Wout, woh, wol, DM);

    // 2. QKV GEMM (HMMA) + fused RoPE + bf16 split scatter
    hmma_gemm_kernel<1><<<dim3(24, 32), 256, mma_sh>>>(
        xhi, xlo, wqh, wql, rc, rs, nullptr);

    // 3. flash attention (HMMA, split precision) -> g_ahi/g_alo
    flash_hmma_kernel<<<dim3(SLEN / 128, BATCH * NHEAD), 256, flash_sh>>>();

    // 4. out-projection GEMM (HMMA)
    hmma_gemm_kernel<0><<<dim3(8, 32), 256, mma_sh>>>(
        ahi, alo, woh, wol, nullptr, nullptr, out);
}

// round 5
// speedup vs baseline: 3.3286x; 1.1022x over previous
#include <cuda_runtime.h>
#include <cuda_bf16.h>
#include <math.h>
#include <stdint.h>

#define SLEN 2048
#define DM   1024
#define NHEAD 16
#define HD   64
#define BATCH 2
#define NROWS (BATCH*SLEN)   // 4096

// ---------------- scratch (device globals; no allocation allowed) ----------
__device__ __nv_bfloat16 g_xhi[(size_t)NROWS*DM];
__device__ __nv_bfloat16 g_xlo[(size_t)NROWS*DM];
__device__ __nv_bfloat16 g_ahi[(size_t)NROWS*DM];
__device__ __nv_bfloat16 g_alo[(size_t)NROWS*DM];
__device__ __nv_bfloat16 g_wqh[(size_t)3*DM*DM];   // W_qkv^T [3072,1024]
__device__ __nv_bfloat16 g_wql[(size_t)3*DM*DM];
__device__ __nv_bfloat16 g_woh[(size_t)DM*DM];     // W_out^T [1024,1024]
__device__ __nv_bfloat16 g_wol[(size_t)DM*DM];
// q/k/v split bf16, layout [B*H][S][64]
__device__ __nv_bfloat16 g_qhi[(size_t)BATCH*NHEAD*SLEN*HD];
__device__ __nv_bfloat16 g_qlo[(size_t)BATCH*NHEAD*SLEN*HD];
__device__ __nv_bfloat16 g_khi[(size_t)BATCH*NHEAD*SLEN*HD];
__device__ __nv_bfloat16 g_klo[(size_t)BATCH*NHEAD*SLEN*HD];
__device__ __nv_bfloat16 g_vhi[(size_t)BATCH*NHEAD*SLEN*HD];
__device__ __nv_bfloat16 g_vlo[(size_t)BATCH*NHEAD*SLEN*HD];

// ---------------- baseline-PTX helpers -------------------------------------
__device__ __forceinline__ uint32_t smem_u32(const void* p) {
    uint32_t a;
    asm("{ .reg .u64 t; cvta.to.shared.u64 t, %1; cvt.u32.u64 %0, t; }"
        : "=r"(a) : "l"(p));
    return a;
}
__device__ __forceinline__ void cp16(uint32_t s, const void* g) {
    asm volatile("cp.async.cg.shared.global [%0], [%1], 16;"
                 :: "r"(s), "l"(g) : "memory");
}
#define CP_COMMIT() asm volatile("cp.async.commit_group;" ::: "memory")
#define CP_WAIT1()  asm volatile("cp.async.wait_group 1;" ::: "memory")
#define CP_WAIT0()  asm volatile("cp.async.wait_group 0;" ::: "memory")

__device__ __forceinline__ void ldsm4(uint32_t* r, uint32_t addr) {
    asm volatile("ldmatrix.sync.aligned.m8n8.x4.shared.b16 {%0,%1,%2,%3}, [%4];"
        : "=r"(r[0]), "=r"(r[1]), "=r"(r[2]), "=r"(r[3]) : "r"(addr));
}
__device__ __forceinline__ void ldsm4t(uint32_t* r, uint32_t addr) {
    asm volatile("ldmatrix.sync.aligned.m8n8.x4.trans.shared.b16 {%0,%1,%2,%3}, [%4];"
        : "=r"(r[0]), "=r"(r[1]), "=r"(r[2]), "=r"(r[3]) : "r"(addr));
}
__device__ __forceinline__ void mma_bf16(float* d, const uint32_t* a,
                                         const uint32_t* b) {
    asm volatile("mma.sync.aligned.m16n8k16.row.col.f32.bf16.bf16.f32 "
        "{%0,%1,%2,%3}, {%4,%5,%6,%7}, {%8,%9}, {%0,%1,%2,%3};"
        : "+f"(d[0]), "+f"(d[1]), "+f"(d[2]), "+f"(d[3])
        : "r"(a[0]), "r"(a[1]), "r"(a[2]), "r"(a[3]), "r"(b[0]), "r"(b[1]));
}
// pack two fp32 -> bf16x2 (lo in low half)
__device__ __forceinline__ uint32_t packbf(float lo, float hi) {
    uint32_t d;
    asm("cvt.rn.bf16x2.f32 %0, %1, %2;" : "=r"(d) : "f"(hi), "f"(lo));
    return d;
}
__device__ __forceinline__ float bflo(uint32_t u) { return __int_as_float(u << 16); }
__device__ __forceinline__ float bfhi(uint32_t u) { return __int_as_float(u & 0xFFFF0000u); }

// exp2 via FFMA poly (no MUFU). z expected <= 0; clamped at -40.
__device__ __forceinline__ float fast_exp2(float z) {
    z = fmaxf(z, -40.f);
    const float km = z + 12582912.f;          // round-to-nearest int
    const int   ki = __float_as_int(km) - 0x4B400000;   // = round(z)
    const float f  = z - (km - 12582912.f);   // frac in [-0.5, 0.5]
    float p = 0.0013333558f;
    p = fmaf(p, f, 0.0096181815f);
    p = fmaf(p, f, 0.0555041087f);
    p = fmaf(p, f, 0.2402265069f);
    p = fmaf(p, f, 0.6931471806f);
    p = fmaf(p, f, 1.0f);
    return p * __int_as_float((ki + 127) << 23);
}

#define SCQ 0.18033688011112042f   // hd^-0.5 * log2(e), folded into Q

// ---------------------------------------------------------------------------
// Convert fp32 -> (bf16 hi, bf16 lo)
// ---------------------------------------------------------------------------
__global__ __launch_bounds__(256) void conv_split_kernel(
    const float* __restrict__ src, __nv_bfloat16* __restrict__ hi,
    __nv_bfloat16* __restrict__ lo, int n)
{
    int i = (blockIdx.x * 256 + threadIdx.x) * 4;
    if (i >= n) return;
    float4 v = *(const float4*)(src + i);
    uint32_t h0 = packbf(v.x, v.y), h1 = packbf(v.z, v.w);
    uint32_t l0 = packbf(v.x - bflo(h0), v.y - bfhi(h0));
    uint32_t l1 = packbf(v.z - bflo(h1), v.w - bfhi(h1));
    uint2* hp = (uint2*)(hi + i); *hp = make_uint2(h0, h1);
    uint2* lp = (uint2*)(lo + i); *lp = make_uint2(l0, l1);
}

// ---------------------------------------------------------------------------
// Transpose + split: W[1024, N] fp32 -> Wt_hi/lo [N, 1024] bf16
// ---------------------------------------------------------------------------
__global__ __launch_bounds__(256) void conv_wt_kernel(
    const float* __restrict__ W, __nv_bfloat16* __restrict__ hi,
    __nv_bfloat16* __restrict__ lo, int N)
{
    __shared__ float t[32][33];
    const int n0 = blockIdx.x * 32, k0 = blockIdx.y * 32;
    const int tx = threadIdx.x & 31, ty = threadIdx.x >> 5;
    #pragma unroll
    for (int i = 0; i < 4; i++)
        t[ty + i * 8][tx] = W[(size_t)(k0 + ty + i * 8) * N + n0 + tx];
    __syncthreads();
    #pragma unroll
    for (int i = 0; i < 4; i++) {
        const int n = n0 + ty + i * 8;
        const float v = t[tx][ty + i * 8];
        __nv_bfloat16 h = __float2bfloat16(v);
        hi[(size_t)n * DM + k0 + tx] = h;
        lo[(size_t)n * DM + k0 + tx] = __float2bfloat16(v - __bfloat162float(h));
    }
}

// ---------------------------------------------------------------------------
// HMMA bf16-split GEMM: D[M,N] = A[M,1024] * B[N,1024]^T, 128x128 CTA tile,
// 8 warps (4m x 2n), warp tile 32x64, K-chunk 32, cp.async double-buffer.
// B fragments loaded just-in-time (8 live regs, not 32) so the kernel fits
// 128 regs -> 2 CTAs/SM; the co-resident CTA hides sync/load bubbles.
// DO_QKV: fused RoPE + bf16 hi/lo split scatter to g_q/k/v (Q pre-scaled).
// ---------------------------------------------------------------------------
template<int DO_QKV>
__global__ __launch_bounds__(256, 2) void hmma_gemm_kernel(
    const __nv_bfloat16* __restrict__ Ahi, const __nv_bfloat16* __restrict__ Alo,
    const __nv_bfloat16* __restrict__ Bhi, const __nv_bfloat16* __restrict__ Blo,
    const float* __restrict__ rc, const float* __restrict__ rs,
    float* __restrict__ outp)
{
    extern __shared__ char smem[];
    const uint32_t sb = smem_u32(smem);
    const int tid = threadIdx.x, lane = tid & 31, wid = tid >> 5;
    const int wm = wid >> 1, wn = wid & 1;
    const int row0 = blockIdx.y * 128, col0 = blockIdx.x * 128;

    float acc[2][8][4];
    #pragma unroll
    for (int m = 0; m < 2; m++)
        #pragma unroll
        for (int n = 0; n < 8; n++)
            #pragma unroll
            for (int q = 0; q < 4; q++) acc[m][n][q] = 0.f;

    const int lrow = tid >> 1, kh = tid & 1;
    const __nv_bfloat16* ga[4];
    ga[0] = Ahi + (size_t)(row0 + lrow) * DM;
    ga[1] = Alo + (size_t)(row0 + lrow) * DM;
    ga[2] = Bhi + (size_t)(col0 + lrow) * DM;
    ga[3] = Blo + (size_t)(col0 + lrow) * DM;

    auto issue = [&](int c, int bi) {
        const int k0 = c * 32;
        const uint32_t buf = sb + bi * 40960;
        #pragma unroll
        for (int a = 0; a < 4; a++) {
            const __nv_bfloat16* gp = ga[a] + k0 + kh * 16;
            const uint32_t so = buf + a * 10240 + lrow * 80 + kh * 32;
            cp16(so,      gp);
            cp16(so + 16, gp + 8);
        }
    };

    issue(0, 0); CP_COMMIT();
    issue(1, 1); CP_COMMIT();

    // per-warp ldmatrix base addresses (buffer-relative)
    const uint32_t aoff = (uint32_t)((wm * 32 + (lane & 15)) * 80
                        + (lane >> 4) * 16);
    const uint32_t boff = (uint32_t)(20480
                        + (wn * 64 + (lane & 7) + ((lane >> 4) << 3)) * 80
                        + ((lane >> 3) & 1) * 16);

    for (int c = 0; c < 32; c++) {
        CP_WAIT1();
        __syncthreads();
        const uint32_t buf = sb + (c & 1) * 40960;
        const uint32_t ab = buf + aoff;
        const uint32_t bb = buf + boff;
        #pragma unroll
        for (int ks = 0; ks < 2; ks++) {
            uint32_t ah[2][4], al[2][4];
            ldsm4(ah[0], ab + ks * 32);
            ldsm4(ah[1], ab + 16 * 80 + ks * 32);
            ldsm4(al[0], ab + 10240 + ks * 32);
            ldsm4(al[1], ab + 10240 + 16 * 80 + ks * 32);
            #pragma unroll
            for (int nf2 = 0; nf2 < 4; nf2++) {
                uint32_t bh4[4], bl4[4];
                ldsm4(bh4, bb + nf2 * 16 * 80 + ks * 32);
                ldsm4(bl4, bb + 10240 + nf2 * 16 * 80 + ks * 32);
                #pragma unroll
                for (int mt = 0; mt < 2; mt++) {
                    mma_bf16(acc[mt][2 * nf2],     ah[mt], bh4);
                    mma_bf16(acc[mt][2 * nf2],     ah[mt], bl4);
                    mma_bf16(acc[mt][2 * nf2],     al[mt], bh4);
                    mma_bf16(acc[mt][2 * nf2 + 1], ah[mt], bh4 + 2);
                    mma_bf16(acc[mt][2 * nf2 + 1], ah[mt], bl4 + 2);
                    mma_bf16(acc[mt][2 * nf2 + 1], al[mt], bh4 + 2);
                }
            }
        }
        __syncthreads();
        if (c + 2 < 32) { issue(c + 2, c & 1); CP_COMMIT(); }
        else            { CP_COMMIT(); }
    }

    // ---------------- epilogue ----------------
    const int l4 = lane >> 2, l2 = (lane & 3) * 2;
    if (DO_QKV) {
        const int part = col0 >> 10;                 // 0=q, 1=k, 2=v
        const int head = ((col0 & 1023) >> 6) + wn;
        __nv_bfloat16* dhi = (part == 0) ? g_qhi : (part == 1) ? g_khi : g_vhi;
        __nv_bfloat16* dlo = (part == 0) ? g_qlo : (part == 1) ? g_klo : g_vlo;
        #pragma unroll
        for (int mt = 0; mt < 2; mt++) {
            #pragma unroll
            for (int rr = 0; rr < 2; rr++) {
                const int grow = row0 + wm * 32 + mt * 16 + l4 + rr * 8;
                const int b = grow >> 11, s = grow & 2047;
                const size_t obase = ((size_t)(b * NHEAD + head) * SLEN + s) * HD;
                const float* rcp = rc + s * 32;
                const float* rsp = rs + s * 32;
                #pragma unroll
                for (int nf = 0; nf < 8; nf++) {
                    const int d = nf * 8 + l2;
                    const float v1 = acc[mt][nf][rr * 2 + 0];
                    const float v2 = acc[mt][nf][rr * 2 + 1];
                    float ox, oy;
                    if (part < 2) {
                        const int pi = d >> 1;
                        const float cth = rcp[pi], sth = rsp[pi];
                        ox = v1 * cth - v2 * sth;
                        oy = v1 * sth + v2 * cth;
                        if (part == 0) { ox *= SCQ; oy *= SCQ; }
                    } else {
                        ox = v1; oy = v2;
                    }
                    const uint32_t hb = packbf(ox, oy);
                    const uint32_t lb = packbf(ox - bflo(hb), oy - bfhi(hb));
                    *(uint32_t*)(dhi + obase + d) = hb;
                    *(uint32_t*)(dlo + obase + d) = lb;
                }
            }
        }
    } else {
        #pragma unroll
        for (int mt = 0; mt < 2; mt++) {
            #pragma unroll
            for (int rr = 0; rr < 2; rr++) {
                const int grow = row0 + wm * 32 + mt * 16 + l4 + rr * 8;
                float* op = outp + (size_t)grow * DM + col0 + wn * 64 + l2;
                #pragma unroll
                for (int nf = 0; nf < 8; nf++) {
                    float2 o;
                    o.x = acc[mt][nf][rr * 2 + 0];
                    o.y = acc[mt][nf][rr * 2 + 1];
                    *(float2*)(op + nf * 8) = o;
                }
            }
        }
    }
}

// ---------------------------------------------------------------------------
// HMMA FlashAttention: BM=128 queries, KN=128 keys/tile, 256 thr (8 warps,
// each warp owns 16 query rows x all 128 key cols). Split-precision bf16
// (hi/lo) for QK and PV; softmax with FFMA exp2; P stays in registers
// (C-fragment layout == A-fragment layout). Writes bf16 hi/lo to g_ahi/g_alo.
// smem: 6 tiles of 128 rows x 72 bf16 (144B stride, conflict-free ldmatrix).
// ---------------------------------------------------------------------------
#define FTILE 18432          // 128*72*2 bytes
__global__ __launch_bounds__(256) void flash_hmma_kernel()
{
    extern __shared__ char fsm[];
    const uint32_t sb = smem_u32(fsm);
    const uint32_t Qh = sb,             Ql = sb + FTILE;
    const uint32_t Kh = sb + 2 * FTILE, Kl = sb + 3 * FTILE;
    const uint32_t Vh = sb + 4 * FTILE, Vl = sb + 5 * FTILE;

    const int tid = threadIdx.x, lane = tid & 31, w = tid >> 5;
    const int qb = gridDim.x - 1 - blockIdx.x;      // long CTAs first
    const int q0 = qb * 128, bh = blockIdx.y;
    const size_t base = (size_t)bh * SLEN * HD;

    const __nv_bfloat16 *qhg = g_qhi + base + (size_t)q0 * HD;
    const __nv_bfloat16 *qlg = g_qlo + base + (size_t)q0 * HD;
    const __nv_bfloat16 *khg = g_khi + base, *klg = g_klo + base;
    const __nv_bfloat16 *vhg = g_vhi + base, *vlg = g_vlo + base;

    auto ldtile = [&](uint32_t dh, uint32_t dl,
                      const __nv_bfloat16* gh, const __nv_bfloat16* gl) {
        #pragma unroll
        for (int kk = 0; kk < 4; kk++) {
            const int c = tid + kk * 256;
            const int row = c >> 3, q8 = c & 7;
            cp16(dh + row * 144 + q8 * 16, gh + row * 64 + q8 * 8);
            cp16(dl + row * 144 + q8 * 16, gl + row * 64 + q8 * 8);
        }
    };

    ldtile(Qh, Ql, qhg, qlg);
    ldtile(Kh, Kl, khg, klg);
    CP_COMMIT();
    ldtile(Vh, Vl, vhg, vlg);
    CP_COMMIT();

    uint32_t qfh[4][4], qfl[4][4];
    float oacc[8][4];
    #pragma unroll
    for (int j = 0; j < 8; j++)
        #pragma unroll
        for (int q = 0; q < 4; q++) oacc[j][q] = 0.f;
    float m0 = -1e30f, m1 = -1e30f, l0 = 0.f, l1 = 0.f;

    const int nkb = qb + 1;
    for (int kb = 0; kb < nkb; kb++) {
        const bool lastt = (kb == nkb - 1);
        CP_WAIT1();
        __syncthreads();
        if (kb == 0) {
            #pragma unroll
            for (int ks = 0; ks < 4; ks++) {
                const uint32_t a = (uint32_t)((w * 16 + (lane & 15)) * 144
                                 + (ks * 16 + (lane >> 4) * 8) * 2);
                ldsm4(qfh[ks], Qh + a);
                ldsm4(qfl[ks], Ql + a);
            }
        }
        // ---- S = Q @ K^T (split precision) ----
        float sacc[16][4];
        #pragma unroll
        for (int j = 0; j < 16; j++)
            #pragma unroll
            for (int q = 0; q < 4; q++) sacc[j][q] = 0.f;
        #pragma unroll
        for (int ks = 0; ks < 4; ks++) {
            #pragma unroll
            for (int p = 0; p < 8; p++) {
                uint32_t kh4[4], kl4[4];
                const uint32_t a = (uint32_t)((p * 16 + (lane & 15)) * 144
                                 + (ks * 16 + (lane >> 4) * 8) * 2);
                ldsm4(kh4, Kh + a);
                ldsm4(kl4, Kl + a);
                uint32_t bh0[2] = {kh4[0], kh4[2]}, bh1[2] = {kh4[1], kh4[3]};
                uint32_t bl0[2] = {kl4[0], kl4[2]}, bl1[2] = {kl4[1], kl4[3]};
                mma_bf16(sacc[2 * p],     qfh[ks], bh0);
                mma_bf16(sacc[2 * p],     qfh[ks], bl0);
                mma_bf16(sacc[2 * p],     qfl[ks], bh0);
                mma_bf16(sacc[2 * p + 1], qfh[ks], bh1);
                mma_bf16(sacc[2 * p + 1], qfh[ks], bl1);
                mma_bf16(sacc[2 * p + 1], qfl[ks], bh1);
            }
        }
        __syncthreads();                 // all warps done reading K smem
        if (!lastt) {
            ldtile(Kh, Kl, khg + (size_t)(kb + 1) * 128 * HD,
                           klg + (size_t)(kb + 1) * 128 * HD);
            CP_COMMIT();
        }

        // ---- softmax (registers only; overlaps with K prefetch) ----
        if (lastt) {  // diagonal tile: mask col > row (tile-local, kb*128==q0)
            const int rl0 = w * 16 + (lane >> 2);
            #pragma unroll
            for (int j = 0; j < 16; j++) {
                const int c = j * 8 + (lane & 3) * 2;
                if (c     > rl0)     sacc[j][0] = -1e30f;
                if (c + 1 > rl0)     sacc[j][1] = -1e30f;
                if (c     > rl0 + 8) sacc[j][2] = -1e30f;
                if (c + 1 > rl0 + 8) sacc[j][3] = -1e30f;
            }
        }
        float rmx0 = -1e30f, rmx1 = -1e30f;
        #pragma unroll
        for (int j = 0; j < 16; j++) {
            rmx0 = fmaxf(rmx0, fmaxf(sacc[j][0], sacc[j][1]));
            rmx1 = fmaxf(rmx1, fmaxf(sacc[j][2], sacc[j][3]));
        }
        rmx0 = fmaxf(rmx0, __shfl_xor_sync(0xffffffffu, rmx0, 1));
        rmx0 = fmaxf(rmx0, __shfl_xor_sync(0xffffffffu, rmx0, 2));
        rmx1 = fmaxf(rmx1, __shfl_xor_sync(0xffffffffu, rmx1, 1));
        rmx1 = fmaxf(rmx1, __shfl_xor_sync(0xffffffffu, rmx1, 2));
        const float mn0 = fmaxf(m0, rmx0), mn1 = fmaxf(m1, rmx1);
        const float rs0 = fast_exp2(m0 - mn0), rs1 = fast_exp2(m1 - mn1);
        m0 = mn0; m1 = mn1;
        float sum0 = 0.f, sum1 = 0.f;
        #pragma unroll
        for (int j = 0; j < 16; j++) {
            sacc[j][0] = fast_exp2(sacc[j][0] - m0);
            sacc[j][1] = fast_exp2(sacc[j][1] - m0);
            sacc[j][2] = fast_exp2(sacc[j][2] - m1);
            sacc[j][3] = fast_exp2(sacc[j][3] - m1);
            sum0 += sacc[j][0] + sacc[j][1];
            sum1 += sacc[j][2] + sacc[j][3];
        }
        sum0 += __shfl_xor_sync(0xffffffffu, sum0, 1);
        sum0 += __shfl_xor_sync(0xffffffffu, sum0, 2);
        sum1 += __shfl_xor_sync(0xffffffffu, sum1, 1);
        sum1 += __shfl_xor_sync(0xffffffffu, sum1, 2);
        l0 = l0 * rs0 + sum0;
        l1 = l1 * rs1 + sum1;
        #pragma unroll
        for (int j = 0; j < 8; j++) {
            oacc[j][0] *= rs0; oacc[j][1] *= rs0;
            oacc[j][2] *= rs1; oacc[j][3] *= rs1;
        }

        // ---- O += P @ V (split precision; P from S accumulators) ----
        if (!lastt) CP_WAIT1(); else CP_WAIT0();
        __syncthreads();
        #pragma unroll
        for (int ks = 0; ks < 8; ks++) {
            const float* s0 = sacc[2 * ks];
            const float* s1 = sacc[2 * ks + 1];
            uint32_t ph[4], pl[4];
            ph[0] = packbf(s0[0], s0[1]); ph[1] = packbf(s0[2], s0[3]);
            ph[2] = packbf(s1[0], s1[1]); ph[3] = packbf(s1[2], s1[3]);
            pl[0] = packbf(s0[0] - bflo(ph[0]), s0[1] - bfhi(ph[0]));
            pl[1] = packbf(s0[2] - bflo(ph[1]), s0[3] - bfhi(ph[1]));
            pl[2] = packbf(s1[0] - bflo(ph[2]), s1[1] - bfhi(ph[2]));
            pl[3] = packbf(s1[2] - bflo(ph[3]), s1[3] - bfhi(ph[3]));
            #pragma unroll
            for (int p = 0; p < 4; p++) {
                uint32_t vh4[4], vl4[4];
                const uint32_t a = (uint32_t)((ks * 16 + (lane & 15)) * 144
                                 + (p * 16 + (lane >> 4) * 8) * 2);
                ldsm4t(vh4, Vh + a);
                ldsm4t(vl4, Vl + a);
                uint32_t bh0[2] = {vh4[0], vh4[1]}, bh1[2] = {vh4[2], vh4[3]};
                uint32_t bl0[2] = {vl4[0], vl4[1]}, bl1[2] = {vl4[2], vl4[3]};
                mma_bf16(oacc[2 * p],     ph, bh0);
                mma_bf16(oacc[2 * p],     ph, bl0);
                mma_bf16(oacc[2 * p],     pl, bh0);
                mma_bf16(oacc[2 * p + 1], ph, bh1);
                mma_bf16(oacc[2 * p + 1], ph, bl1);
                mma_bf16(oacc[2 * p + 1], pl, bh1);
            }
        }
        __syncthreads();                 // all warps done reading V smem
        if (!lastt) {
            ldtile(Vh, Vl, vhg + (size_t)(kb + 1) * 128 * HD,
                           vlg + (size_t)(kb + 1) * 128 * HD);
            CP_COMMIT();
        }
    }

    // ---- epilogue: normalize, split to bf16 hi/lo, write [B,S,D] ----
    const float inv0 = 1.f / l0, inv1 = 1.f / l1;
    const int b = bh >> 4, h = bh & 15;
    const int s0r = q0 + w * 16 + (lane >> 2);
    const size_t rowA = (size_t)(b * SLEN + s0r);
    const size_t rowB = rowA + 8;
    const int colb = h * 64 + (lane & 3) * 2;
    #pragma unroll
    for (int j = 0; j < 8; j++) {
        const int col = colb + j * 8;
        const float x0 = oacc[j][0] * inv0, x1 = oacc[j][1] * inv0;
        const float y0 = oacc[j][2] * inv1, y1 = oacc[j][3] * inv1;
        uint32_t hb = packbf(x0, x1);
        uint32_t lb = packbf(x0 - bflo(hb), x1 - bfhi(hb));
        *(uint32_t*)(g_ahi + rowA * DM + col) = hb;
        *(uint32_t*)(g_alo + rowA * DM + col) = lb;
        hb = packbf(y0, y1);
        lb = packbf(y0 - bflo(hb), y1 - bfhi(hb));
        *(uint32_t*)(g_ahi + rowB * DM + col) = hb;
        *(uint32_t*)(g_alo + rowB * DM + col) = lb;
    }
}

// ---------------------------------------------------------------------------
extern "C" void kernel_launch(void* const* d_in, const int* in_sizes, int n_in,
                              void* d_out, int out_size)
{
    const float* x    = (const float*)d_in[0];
    const float* rc   = (const float*)d_in[1];
    const float* rs   = (const float*)d_in[2];
    const float* Wqkv = (const float*)d_in[3];
    const float* Wout = (const float*)d_in[4];
    float* out = (float*)d_out;

    const size_t mma_sh   = 81920;
    const size_t flash_sh = 6 * FTILE;   // 110592
    cudaFuncSetAttribute(hmma_gemm_kernel<1>,
        cudaFuncAttributeMaxDynamicSharedMemorySize, (int)mma_sh);
    cudaFuncSetAttribute(hmma_gemm_kernel<0>,
        cudaFuncAttributeMaxDynamicSharedMemorySize, (int)mma_sh);
    cudaFuncSetAttribute(flash_hmma_kernel,
        cudaFuncAttributeMaxDynamicSharedMemorySize, (int)flash_sh);

    __nv_bfloat16 *xhi, *xlo, *ahi, *alo, *wqh, *wql, *woh, *wol;
    cudaGetSymbolAddress((void**)&xhi, g_xhi);
    cudaGetSymbolAddress((void**)&xlo, g_xlo);
    cudaGetSymbolAddress((void**)&ahi, g_ahi);
    cudaGetSymbolAddress((void**)&alo, g_alo);
    cudaGetSymbolAddress((void**)&wqh, g_wqh);
    cudaGetSymbolAddress((void**)&wql, g_wql);
    cudaGetSymbolAddress((void**)&woh, g_woh);
    cudaGetSymbolAddress((void**)&wol, g_wol);

    // 1. splits / transposes
    conv_split_kernel<<<(NROWS * DM) / 1024, 256>>>(x, xhi, xlo, NROWS * DM);
    conv_wt_kernel<<<dim3(96, 32), 256>>>(Wqkv, wqh, wql, 3 * DM);
    conv_wt_kernel<<<dim3(32, 32), 256>>>(Wout, woh, wol, DM);

    // 2. QKV GEMM (HMMA) + fused RoPE + bf16 split scatter
    hmma_gemm_kernel<1><<<dim3(24, 32), 256, mma_sh>>>(
        xhi, xlo, wqh, wql, rc, rs, nullptr);

    // 3. flash attention (HMMA, split precision) -> g_ahi/g_alo
    flash_hmma_kernel<<<dim3(SLEN / 128, BATCH * NHEAD), 256, flash_sh>>>();

    // 4. out-projection GEMM (HMMA)
    hmma_gemm_kernel<0><<<dim3(8, 32), 256, mma_sh>>>(
        ahi, alo, woh, wol, nullptr, nullptr, out);
}

// round 8
// speedup vs baseline: 3.5153x; 1.0561x over previous
#include <cuda_runtime.h>
#include <cuda_bf16.h>
#include <math.h>
#include <stdint.h>

#define SLEN 2048
#define DM   1024
#define NHEAD 16
#define HD   64
#define BATCH 2
#define NROWS (BATCH*SLEN)   // 4096

// ---------------- scratch (device globals; no allocation allowed) ----------
__device__ __nv_bfloat16 g_xhi[(size_t)NROWS*DM];
__device__ __nv_bfloat16 g_xlo[(size_t)NROWS*DM];
__device__ __nv_bfloat16 g_ahi[(size_t)NROWS*DM];
__device__ __nv_bfloat16 g_alo[(size_t)NROWS*DM];
__device__ __nv_bfloat16 g_wqh[(size_t)3*DM*DM];   // W_qkv^T [3072,1024]
__device__ __nv_bfloat16 g_wql[(size_t)3*DM*DM];
__device__ __nv_bfloat16 g_woh[(size_t)DM*DM];     // W_out^T [1024,1024]
__device__ __nv_bfloat16 g_wol[(size_t)DM*DM];
// q/k/v split bf16, layout [B*H][S][64]
__device__ __nv_bfloat16 g_qhi[(size_t)BATCH*NHEAD*SLEN*HD];
__device__ __nv_bfloat16 g_qlo[(size_t)BATCH*NHEAD*SLEN*HD];
__device__ __nv_bfloat16 g_khi[(size_t)BATCH*NHEAD*SLEN*HD];
__device__ __nv_bfloat16 g_klo[(size_t)BATCH*NHEAD*SLEN*HD];
__device__ __nv_bfloat16 g_vhi[(size_t)BATCH*NHEAD*SLEN*HD];
__device__ __nv_bfloat16 g_vlo[(size_t)BATCH*NHEAD*SLEN*HD];

// ---------------- baseline-PTX helpers -------------------------------------
__device__ __forceinline__ uint32_t smem_u32(const void* p) {
    uint32_t a;
    asm("{ .reg .u64 t; cvta.to.shared.u64 t, %1; cvt.u32.u64 %0, t; }"
        : "=r"(a) : "l"(p));
    return a;
}
__device__ __forceinline__ void cp16(uint32_t s, const void* g) {
    asm volatile("cp.async.cg.shared.global [%0], [%1], 16;"
                 :: "r"(s), "l"(g) : "memory");
}
#define CP_COMMIT() asm volatile("cp.async.commit_group;" ::: "memory")
#define CP_WAIT2()  asm volatile("cp.async.wait_group 2;" ::: "memory")
#define CP_WAIT1()  asm volatile("cp.async.wait_group 1;" ::: "memory")
#define CP_WAIT0()  asm volatile("cp.async.wait_group 0;" ::: "memory")

__device__ __forceinline__ void ldsm4(uint32_t* r, uint32_t addr) {
    asm volatile("ldmatrix.sync.aligned.m8n8.x4.shared.b16 {%0,%1,%2,%3}, [%4];"
        : "=r"(r[0]), "=r"(r[1]), "=r"(r[2]), "=r"(r[3]) : "r"(addr));
}
__device__ __forceinline__ void ldsm4t(uint32_t* r, uint32_t addr) {
    asm volatile("ldmatrix.sync.aligned.m8n8.x4.trans.shared.b16 {%0,%1,%2,%3}, [%4];"
        : "=r"(r[0]), "=r"(r[1]), "=r"(r[2]), "=r"(r[3]) : "r"(addr));
}
__device__ __forceinline__ void mma_bf16(float* d, const uint32_t* a,
                                         const uint32_t* b) {
    asm volatile("mma.sync.aligned.m16n8k16.row.col.f32.bf16.bf16.f32 "
        "{%0,%1,%2,%3}, {%4,%5,%6,%7}, {%8,%9}, {%0,%1,%2,%3};"
        : "+f"(d[0]), "+f"(d[1]), "+f"(d[2]), "+f"(d[3])
        : "r"(a[0]), "r"(a[1]), "r"(a[2]), "r"(a[3]), "r"(b[0]), "r"(b[1]));
}
// pack two fp32 -> bf16x2 (lo in low half)
__device__ __forceinline__ uint32_t packbf(float lo, float hi) {
    uint32_t d;
    asm("cvt.rn.bf16x2.f32 %0, %1, %2;" : "=r"(d) : "f"(hi), "f"(lo));
    return d;
}
__device__ __forceinline__ float bflo(uint32_t u) { return __int_as_float(u << 16); }
__device__ __forceinline__ float bfhi(uint32_t u) { return __int_as_float(u & 0xFFFF0000u); }

// exp2 via FFMA poly (no MUFU). z expected <= 0; clamped at -40.
__device__ __forceinline__ float fast_exp2(float z) {
    z = fmaxf(z, -40.f);
    const float km = z + 12582912.f;          // round-to-nearest int
    const int   ki = __float_as_int(km) - 0x4B400000;   // = round(z)
    const float f  = z - (km - 12582912.f);   // frac in [-0.5, 0.5]
    float p = 0.0013333558f;
    p = fmaf(p, f, 0.0096181815f);
    p = fmaf(p, f, 0.0555041087f);
    p = fmaf(p, f, 0.2402265069f);
    p = fmaf(p, f, 0.6931471806f);
    p = fmaf(p, f, 1.0f);
    return p * __int_as_float((ki + 127) << 23);
}

#define SCQ 0.18033688011112042f   // hd^-0.5 * log2(e), folded into Q

// ---------------------------------------------------------------------------
// Convert fp32 -> (bf16 hi, bf16 lo)
// ---------------------------------------------------------------------------
__global__ __launch_bounds__(256) void conv_split_kernel(
    const float* __restrict__ src, __nv_bfloat16* __restrict__ hi,
    __nv_bfloat16* __restrict__ lo, int n)
{
    int i = (blockIdx.x * 256 + threadIdx.x) * 4;
    if (i >= n) return;
    float4 v = *(const float4*)(src + i);
    uint32_t h0 = packbf(v.x, v.y), h1 = packbf(v.z, v.w);
    uint32_t l0 = packbf(v.x - bflo(h0), v.y - bfhi(h0));
    uint32_t l1 = packbf(v.z - bflo(h1), v.w - bfhi(h1));
    uint2* hp = (uint2*)(hi + i); *hp = make_uint2(h0, h1);
    uint2* lp = (uint2*)(lo + i); *lp = make_uint2(l0, l1);
}

// ---------------------------------------------------------------------------
// Transpose + split: W[1024, N] fp32 -> Wt_hi/lo [N, 1024] bf16
// ---------------------------------------------------------------------------
__global__ __launch_bounds__(256) void conv_wt_kernel(
    const float* __restrict__ W, __nv_bfloat16* __restrict__ hi,
    __nv_bfloat16* __restrict__ lo, int N)
{
    __shared__ float t[32][33];
    const int n0 = blockIdx.x * 32, k0 = blockIdx.y * 32;
    const int tx = threadIdx.x & 31, ty = threadIdx.x >> 5;
    #pragma unroll
    for (int i = 0; i < 4; i++)
        t[ty + i * 8][tx] = W[(size_t)(k0 + ty + i * 8) * N + n0 + tx];
    __syncthreads();
    #pragma unroll
    for (int i = 0; i < 4; i++) {
        const int n = n0 + ty + i * 8;
        const float v = t[tx][ty + i * 8];
        __nv_bfloat16 h = __float2bfloat16(v);
        hi[(size_t)n * DM + k0 + tx] = h;
        lo[(size_t)n * DM + k0 + tx] = __float2bfloat16(v - __bfloat162float(h));
    }
}

// ---------------------------------------------------------------------------
// HMMA bf16-split GEMM: D[M,N] = A[M,1024] * B[N,1024]^T, 128x128 CTA tile,
// 8 warps (4m x 2n), m16n8k16, K-chunk 16, 4-stage cp.async pipeline with a
// SINGLE __syncthreads per chunk (issue into the buffer freed by chunk c-1).
// Stage = 4 arrays x 128 rows x 48B = 24576B; 4 stages = 96KB -> 2 CTAs/SM.
// DO_QKV: fused RoPE + bf16 hi/lo split scatter to g_q/k/v (Q pre-scaled).
// ---------------------------------------------------------------------------
#define GST   24576
#define GARR  6144
template<int DO_QKV>
__global__ __launch_bounds__(256, 2) void hmma_gemm_kernel(
    const __nv_bfloat16* __restrict__ Ahi, const __nv_bfloat16* __restrict__ Alo,
    const __nv_bfloat16* __restrict__ Bhi, const __nv_bfloat16* __restrict__ Blo,
    const float* __restrict__ rc, const float* __restrict__ rs,
    float* __restrict__ outp)
{
    extern __shared__ char smem[];
    const uint32_t sb = smem_u32(smem);
    const int tid = threadIdx.x, lane = tid & 31, wid = tid >> 5;
    const int wm = wid >> 1, wn = wid & 1;
    const int row0 = blockIdx.y * 128, col0 = blockIdx.x * 128;

    float acc[2][8][4];
    #pragma unroll
    for (int m = 0; m < 2; m++)
        #pragma unroll
        for (int n = 0; n < 8; n++)
            #pragma unroll
            for (int q = 0; q < 4; q++) acc[m][n][q] = 0.f;

    const int lrow = tid >> 1, kh = tid & 1;
    const __nv_bfloat16* ga[4];
    ga[0] = Ahi + (size_t)(row0 + lrow) * DM + kh * 8;
    ga[1] = Alo + (size_t)(row0 + lrow) * DM + kh * 8;
    ga[2] = Bhi + (size_t)(col0 + lrow) * DM + kh * 8;
    ga[3] = Blo + (size_t)(col0 + lrow) * DM + kh * 8;
    const uint32_t ldst = lrow * 48 + kh * 16;

    auto issue = [&](int c) {
        const uint32_t buf = sb + (c & 3) * GST;
        const int k0 = c * 16;
        #pragma unroll
        for (int a = 0; a < 4; a++)
            cp16(buf + a * GARR + ldst, ga[a] + k0);
    };

    issue(0); CP_COMMIT();
    issue(1); CP_COMMIT();
    issue(2); CP_COMMIT();

    const uint32_t aoff = (uint32_t)((wm * 32 + (lane & 15)) * 48
                        + (lane >> 4) * 16);
    const uint32_t boff = (uint32_t)(2 * GARR
                        + (wn * 64 + (lane & 7) + ((lane >> 4) << 3)) * 48
                        + ((lane >> 3) & 1) * 16);

    for (int c = 0; c < 64; c++) {
        CP_WAIT2();
        __syncthreads();
        if (c + 3 < 64) issue(c + 3);
        CP_COMMIT();
        const uint32_t buf = sb + (c & 3) * GST;
        const uint32_t ab = buf + aoff;
        const uint32_t bb = buf + boff;
        uint32_t ah[2][4], al[2][4];
        ldsm4(ah[0], ab);
        ldsm4(ah[1], ab + 16 * 48);
        ldsm4(al[0], ab + GARR);
        ldsm4(al[1], ab + GARR + 16 * 48);
        #pragma unroll
        for (int nf2 = 0; nf2 < 4; nf2++) {
            uint32_t bh4[4], bl4[4];
            ldsm4(bh4, bb + nf2 * 16 * 48);
            ldsm4(bl4, bb + GARR + nf2 * 16 * 48);
            #pragma unroll
            for (int mt = 0; mt < 2; mt++) {
                mma_bf16(acc[mt][2 * nf2],     ah[mt], bh4);
                mma_bf16(acc[mt][2 * nf2],     ah[mt], bl4);
                mma_bf16(acc[mt][2 * nf2],     al[mt], bh4);
                mma_bf16(acc[mt][2 * nf2 + 1], ah[mt], bh4 + 2);
                mma_bf16(acc[mt][2 * nf2 + 1], ah[mt], bl4 + 2);
                mma_bf16(acc[mt][2 * nf2 + 1], al[mt], bh4 + 2);
            }
        }
    }

    // ---------------- epilogue ----------------
    const int l4 = lane >> 2, l2 = (lane & 3) * 2;
    if (DO_QKV) {
        const int part = col0 >> 10;                 // 0=q, 1=k, 2=v
        const int head = ((col0 & 1023) >> 6) + wn;
        __nv_bfloat16* dhi = (part == 0) ? g_qhi : (part == 1) ? g_khi : g_vhi;
        __nv_bfloat16* dlo = (part == 0) ? g_qlo : (part == 1) ? g_klo : g_vlo;
        #pragma unroll
        for (int mt = 0; mt < 2; mt++) {
            #pragma unroll
            for (int rr = 0; rr < 2; rr++) {
                const int grow = row0 + wm * 32 + mt * 16 + l4 + rr * 8;
                const int b = grow >> 11, s = grow & 2047;
                const size_t obase = ((size_t)(b * NHEAD + head) * SLEN + s) * HD;
                const float* rcp = rc + s * 32;
                const float* rsp = rs + s * 32;
                #pragma unroll
                for (int nf = 0; nf < 8; nf++) {
                    const int d = nf * 8 + l2;
                    const float v1 = acc[mt][nf][rr * 2 + 0];
                    const float v2 = acc[mt][nf][rr * 2 + 1];
                    float ox, oy;
                    if (part < 2) {
                        const int pi = d >> 1;
                        const float cth = rcp[pi], sth = rsp[pi];
                        ox = v1 * cth - v2 * sth;
                        oy = v1 * sth + v2 * cth;
                        if (part == 0) { ox *= SCQ; oy *= SCQ; }
                    } else {
                        ox = v1; oy = v2;
                    }
                    const uint32_t hb = packbf(ox, oy);
                    const uint32_t lb = packbf(ox - bflo(hb), oy - bfhi(hb));
                    *(uint32_t*)(dhi + obase + d) = hb;
                    *(uint32_t*)(dlo + obase + d) = lb;
                }
            }
        }
    } else {
        #pragma unroll
        for (int mt = 0; mt < 2; mt++) {
            #pragma unroll
            for (int rr = 0; rr < 2; rr++) {
                const int grow = row0 + wm * 32 + mt * 16 + l4 + rr * 8;
                float* op = outp + (size_t)grow * DM + col0 + wn * 64 + l2;
                #pragma unroll
                for (int nf = 0; nf < 8; nf++) {
                    float2 o;
                    o.x = acc[mt][nf][rr * 2 + 0];
                    o.y = acc[mt][nf][rr * 2 + 1];
                    *(float2*)(op + nf * 8) = o;
                }
            }
        }
    }
}

// ---------------------------------------------------------------------------
// HMMA FlashAttention: BM=128 queries, KN=128 keys/tile, 256 thr (8 warps,
// each warp owns 16 query rows x all 128 key cols). Split-precision bf16 for
// QK (3 MMAs) and PV (6 MMAs: ph@vh, ph@vl, pl@vh). FFMA exp2 softmax.
// Diagonal tiles skip fully-masked groups (p > w in S, ks > w in PV; exact).
// ---------------------------------------------------------------------------
#define FTILE 18432          // 128*72*2 bytes
__global__ __launch_bounds__(256) void flash_hmma_kernel()
{
    extern __shared__ char fsm[];
    const uint32_t sb = smem_u32(fsm);
    const uint32_t Qh = sb,             Ql = sb + FTILE;
    const uint32_t Kh = sb + 2 * FTILE, Kl = sb + 3 * FTILE;
    const uint32_t Vh = sb + 4 * FTILE, Vl = sb + 5 * FTILE;

    const int tid = threadIdx.x, lane = tid & 31, w = tid >> 5;
    const int qb = gridDim.x - 1 - blockIdx.x;      // long CTAs first
    const int q0 = qb * 128, bh = blockIdx.y;
    const size_t base = (size_t)bh * SLEN * HD;

    const __nv_bfloat16 *qhg = g_qhi + base + (size_t)q0 * HD;
    const __nv_bfloat16 *qlg = g_qlo + base + (size_t)q0 * HD;
    const __nv_bfloat16 *khg = g_khi + base, *klg = g_klo + base;
    const __nv_bfloat16 *vhg = g_vhi + base, *vlg = g_vlo + base;

    auto ldtile = [&](uint32_t dh, uint32_t dl,
                      const __nv_bfloat16* gh, const __nv_bfloat16* gl) {
        #pragma unroll
        for (int kk = 0; kk < 4; kk++) {
            const int c = tid + kk * 256;
            const int row = c >> 3, q8 = c & 7;
            cp16(dh + row * 144 + q8 * 16, gh + row * 64 + q8 * 8);
            cp16(dl + row * 144 + q8 * 16, gl + row * 64 + q8 * 8);
        }
    };

    ldtile(Qh, Ql, qhg, qlg);
    ldtile(Kh, Kl, khg, klg);
    CP_COMMIT();
    ldtile(Vh, Vl, vhg, vlg);
    CP_COMMIT();

    uint32_t qfh[4][4], qfl[4][4];
    float oacc[8][4];
    #pragma unroll
    for (int j = 0; j < 8; j++)
        #pragma unroll
        for (int q = 0; q < 4; q++) oacc[j][q] = 0.f;
    float m0 = -1e30f, m1 = -1e30f, l0 = 0.f, l1 = 0.f;

    const int nkb = qb + 1;
    for (int kb = 0; kb < nkb; kb++) {
        const bool lastt = (kb == nkb - 1);
        CP_WAIT1();
        __syncthreads();
        if (kb == 0) {
            #pragma unroll
            for (int ks = 0; ks < 4; ks++) {
                const uint32_t a = (uint32_t)((w * 16 + (lane & 15)) * 144
                                 + (ks * 16 + (lane >> 4) * 8) * 2);
                ldsm4(qfh[ks], Qh + a);
                ldsm4(qfl[ks], Ql + a);
            }
        }
        // ---- S = Q @ K^T (split precision, 3 MMAs) ----
        float sacc[16][4];
        #pragma unroll
        for (int j = 0; j < 16; j++)
            #pragma unroll
            for (int q = 0; q < 4; q++) sacc[j][q] = 0.f;
        #pragma unroll
        for (int ks = 0; ks < 4; ks++) {
            #pragma unroll
            for (int p = 0; p < 8; p++) {
                if (lastt && p > w) continue;        // fully-masked col group
                uint32_t kh4[4], kl4[4];
                const uint32_t a = (uint32_t)((p * 16 + (lane & 15)) * 144
                                 + (ks * 16 + (lane >> 4) * 8) * 2);
                ldsm4(kh4, Kh + a);
                ldsm4(kl4, Kl + a);
                uint32_t bh0[2] = {kh4[0], kh4[2]}, bh1[2] = {kh4[1], kh4[3]};
                uint32_t bl0[2] = {kl4[0], kl4[2]}, bl1[2] = {kl4[1], kl4[3]};
                mma_bf16(sacc[2 * p],     qfh[ks], bh0);
                mma_bf16(sacc[2 * p],     qfh[ks], bl0);
                mma_bf16(sacc[2 * p],     qfl[ks], bh0);
                mma_bf16(sacc[2 * p + 1], qfh[ks], bh1);
                mma_bf16(sacc[2 * p + 1], qfh[ks], bl1);
                mma_bf16(sacc[2 * p + 1], qfl[ks], bh1);
            }
        }
        __syncthreads();                 // all warps done reading K smem
        if (!lastt) {
            ldtile(Kh, Kl, khg + (size_t)(kb + 1) * 128 * HD,
                           klg + (size_t)(kb + 1) * 128 * HD);
            CP_COMMIT();
        }

        // ---- softmax (registers only; overlaps with K prefetch) ----
        if (lastt) {  // diagonal tile: mask col > row (tile-local, kb*128==q0)
            const int rl0 = w * 16 + (lane >> 2);
            #pragma unroll
            for (int j = 0; j < 16; j++) {
                const int c = j * 8 + (lane & 3) * 2;
                if (c     > rl0)     sacc[j][0] = -1e30f;
                if (c + 1 > rl0)     sacc[j][1] = -1e30f;
                if (c     > rl0 + 8) sacc[j][2] = -1e30f;
                if (c + 1 > rl0 + 8) sacc[j][3] = -1e30f;
            }
        }
        float rmx0 = -1e30f, rmx1 = -1e30f;
        #pragma unroll
        for (int j = 0; j < 16; j++) {
            rmx0 = fmaxf(rmx0, fmaxf(sacc[j][0], sacc[j][1]));
            rmx1 = fmaxf(rmx1, fmaxf(sacc[j][2], sacc[j][3]));
        }
        rmx0 = fmaxf(rmx0, __shfl_xor_sync(0xffffffffu, rmx0, 1));
        rmx0 = fmaxf(rmx0, __shfl_xor_sync(0xffffffffu, rmx0, 2));
        rmx1 = fmaxf(rmx1, __shfl_xor_sync(0xffffffffu, rmx1, 1));
        rmx1 = fmaxf(rmx1, __shfl_xor_sync(0xffffffffu, rmx1, 2));
        const float mn0 = fmaxf(m0, rmx0), mn1 = fmaxf(m1, rmx1);
        const float rs0 = fast_exp2(m0 - mn0), rs1 = fast_exp2(m1 - mn1);
        m0 = mn0; m1 = mn1;
        float sum0 = 0.f, sum1 = 0.f;
        #pragma unroll
        for (int j = 0; j < 16; j++) {
            sacc[j][0] = fast_exp2(sacc[j][0] - m0);
            sacc[j][1] = fast_exp2(sacc[j][1] - m0);
            sacc[j][2] = fast_exp2(sacc[j][2] - m1);
            sacc[j][3] = fast_exp2(sacc[j][3] - m1);
            sum0 += sacc[j][0] + sacc[j][1];
            sum1 += sacc[j][2] + sacc[j][3];
        }
        sum0 += __shfl_xor_sync(0xffffffffu, sum0, 1);
        sum0 += __shfl_xor_sync(0xffffffffu, sum0, 2);
        sum1 += __shfl_xor_sync(0xffffffffu, sum1, 1);
        sum1 += __shfl_xor_sync(0xffffffffu, sum1, 2);
        l0 = l0 * rs0 + sum0;
        l1 = l1 * rs1 + sum1;
        #pragma unroll
        for (int j = 0; j < 8; j++) {
            oacc[j][0] *= rs0; oacc[j][1] *= rs0;
            oacc[j][2] *= rs1; oacc[j][3] *= rs1;
        }

        // ---- O += P @ V (split precision, 6 MMAs; P from S accumulators) ----
        if (!lastt) CP_WAIT1(); else CP_WAIT0();
        __syncthreads();
        #pragma unroll
        for (int ks = 0; ks < 8; ks++) {
            if (lastt && ks > w) continue;           // P ~ 0 beyond diagonal
            const float* s0 = sacc[2 * ks];
            const float* s1 = sacc[2 * ks + 1];
            uint32_t ph[4], pl[4];
            ph[0] = packbf(s0[0], s0[1]); ph[1] = packbf(s0[2], s0[3]);
            ph[2] = packbf(s1[0], s1[1]); ph[3] = packbf(s1[2], s1[3]);
            pl[0] = packbf(s0[0] - bflo(ph[0]), s0[1] - bfhi(ph[0]));
            pl[1] = packbf(s0[2] - bflo(ph[1]), s0[3] - bfhi(ph[1]));
            pl[2] = packbf(s1[0] - bflo(ph[2]), s1[1] - bfhi(ph[2]));
            pl[3] = packbf(s1[2] - bflo(ph[3]), s1[3] - bfhi(ph[3]));
            #pragma unroll
            for (int p = 0; p < 4; p++) {
                uint32_t vh4[4], vl4[4];
                const uint32_t a = (uint32_t)((ks * 16 + (lane & 15)) * 144
                                 + (p * 16 + (lane >> 4) * 8) * 2);
                ldsm4t(vh4, Vh + a);
                ldsm4t(vl4, Vl + a);
                uint32_t bh0[2] = {vh4[0], vh4[1]}, bh1[2] = {vh4[2], vh4[3]};
                uint32_t bl0[2] = {vl4[0], vl4[1]}, bl1[2] = {vl4[2], vl4[3]};
                mma_bf16(oacc[2 * p],     ph, bh0);
                mma_bf16(oacc[2 * p],     ph, bl0);
                mma_bf16(oacc[2 * p],     pl, bh0);
                mma_bf16(oacc[2 * p + 1], ph, bh1);
                mma_bf16(oacc[2 * p + 1], ph, bl1);
                mma_bf16(oacc[2 * p + 1], pl, bh1);
            }
        }
        __syncthreads();                 // all warps done reading V smem
        if (!lastt) {
            ldtile(Vh, Vl, vhg + (size_t)(kb + 1) * 128 * HD,
                           vlg + (size_t)(kb + 1) * 128 * HD);
            CP_COMMIT();
        }
    }

    // ---- epilogue: normalize, split to bf16 hi/lo, write [B,S,D] ----
    const float inv0 = 1.f / l0, inv1 = 1.f / l1;
    const int b = bh >> 4, h = bh & 15;
    const int s0r = q0 + w * 16 + (lane >> 2);
    const size_t rowA = (size_t)(b * SLEN + s0r);
    const size_t rowB = rowA + 8;
    const int colb = h * 64 + (lane & 3) * 2;
    #pragma unroll
    for (int j = 0; j < 8; j++) {
        const int col = colb + j * 8;
        const float x0 = oacc[j][0] * inv0, x1 = oacc[j][1] * inv0;
        const float y0 = oacc[j][2] * inv1, y1 = oacc[j][3] * inv1;
        uint32_t hb = packbf(x0, x1);
        uint32_t lb = packbf(x0 - bflo(hb), x1 - bfhi(hb));
        *(uint32_t*)(g_ahi + rowA * DM + col) = hb;
        *(uint32_t*)(g_alo + rowA * DM + col) = lb;
        hb = packbf(y0, y1);
        lb = packbf(y0 - bflo(hb), y1 - bfhi(hb));
        *(uint32_t*)(g_ahi + rowB * DM + col) = hb;
        *(uint32_t*)(g_alo + rowB * DM + col) = lb;
    }
}

// ---------------------------------------------------------------------------
extern "C" void kernel_launch(void* const* d_in, const int* in_sizes, int n_in,
                              void* d_out, int out_size)
{
    const float* x    = (const float*)d_in[0];
    const float* rc   = (const float*)d_in[1];
    const float* rs   = (const float*)d_in[2];
    const float* Wqkv = (const float*)d_in[3];
    const float* Wout = (const float*)d_in[4];
    float* out = (float*)d_out;

    const size_t mma_sh   = 4 * GST;     // 98304
    const size_t flash_sh = 6 * FTILE;   // 110592
    cudaFuncSetAttribute(hmma_gemm_kernel<1>,
        cudaFuncAttributeMaxDynamicSharedMemorySize, (int)mma_sh);
    cudaFuncSetAttribute(hmma_gemm_kernel<0>,
        cudaFuncAttributeMaxDynamicSharedMemorySize, (int)mma_sh);
    cudaFuncSetAttribute(flash_hmma_kernel,
        cudaFuncAttributeMaxDynamicSharedMemorySize, (int)flash_sh);

    __nv_bfloat16 *xhi, *xlo, *ahi, *alo, *wqh, *wql, *woh, *wol;
    cudaGetSymbolAddress((void**)&xhi, g_xhi);
    cudaGetSymbolAddress((void**)&xlo, g_xlo);
    cudaGetSymbolAddress((void**)&ahi, g_ahi);
    cudaGetSymbolAddress((void**)&alo, g_alo);
    cudaGetSymbolAddress((void**)&wqh, g_wqh);
    cudaGetSymbolAddress((void**)&wql, g_wql);
    cudaGetSymbolAddress((void**)&woh, g_woh);
    cudaGetSymbolAddress((void**)&wol, g_wol);

    // 1. splits / transposes
    conv_split_kernel<<<(NROWS * DM) / 1024, 256>>>(x, xhi, xlo, NROWS * DM);
    conv_wt_kernel<<<dim3(96, 32), 256>>>(Wqkv, wqh, wql, 3 * DM);
    conv_wt_kernel<<<dim3(32, 32), 256>>>(Wout, woh, wol, DM);

    // 2. QKV GEMM (HMMA) + fused RoPE + bf16 split scatter
    hmma_gemm_kernel<1><<<dim3(24, 32), 256, mma_sh>>>(
        xhi, xlo, wqh, wql, rc, rs, nullptr);

    // 3. flash attention (HMMA, split precision) -> g_ahi/g_alo
    flash_hmma_kernel<<<dim3(SLEN / 128, BATCH * NHEAD), 256, flash_sh>>>();

    // 4. out-projection GEMM (HMMA)
    hmma_gemm_kernel<0><<<dim3(8, 32), 256, mma_sh>>>(
        ahi, alo, woh, wol, nullptr, nullptr, out);
}

// round 10
// speedup vs baseline: 4.5836x; 1.3039x over previous
#include <cuda_runtime.h>
#include <cuda_fp16.h>
#include <math.h>
#include <stdint.h>

#define SLEN 2048
#define DM   1024
#define NHEAD 16
#define HD   64
#define BATCH 2
#define NROWS (BATCH*SLEN)   // 4096

// ---------------- scratch (device globals; no allocation allowed) ----------
__device__ __half g_xh[(size_t)NROWS*DM];          // x fp16
__device__ __half g_ah[(size_t)NROWS*DM];          // attn out fp16
__device__ __half g_wqh[(size_t)3*DM*DM];          // (32*W_qkv)^T hi [3072,1024]
__device__ __half g_wql[(size_t)3*DM*DM];          // lo
__device__ __half g_woh[(size_t)DM*DM];            // (32*W_out)^T hi
__device__ __half g_wol[(size_t)DM*DM];
// q/k/v fp16, layout [B*H][S][64]; k,v keep lo (B-side operands)
__device__ __half g_qh[(size_t)BATCH*NHEAD*SLEN*HD];
__device__ __half g_kh[(size_t)BATCH*NHEAD*SLEN*HD];
__device__ __half g_kl[(size_t)BATCH*NHEAD*SLEN*HD];
__device__ __half g_vh[(size_t)BATCH*NHEAD*SLEN*HD];
__device__ __half g_vl[(size_t)BATCH*NHEAD*SLEN*HD];

// ---------------- baseline-PTX helpers -------------------------------------
__device__ __forceinline__ uint32_t smem_u32(const void* p) {
    uint32_t a;
    asm("{ .reg .u64 t; cvta.to.shared.u64 t, %1; cvt.u32.u64 %0, t; }"
        : "=r"(a) : "l"(p));
    return a;
}
__device__ __forceinline__ void cp16(uint32_t s, const void* g) {
    asm volatile("cp.async.cg.shared.global [%0], [%1], 16;"
                 :: "r"(s), "l"(g) : "memory");
}
#define CP_COMMIT() asm volatile("cp.async.commit_group;" ::: "memory")
#define CP_WAIT2()  asm volatile("cp.async.wait_group 2;" ::: "memory")
#define CP_WAIT1()  asm volatile("cp.async.wait_group 1;" ::: "memory")
#define CP_WAIT0()  asm volatile("cp.async.wait_group 0;" ::: "memory")

__device__ __forceinline__ void ldsm4(uint32_t* r, uint32_t addr) {
    asm volatile("ldmatrix.sync.aligned.m8n8.x4.shared.b16 {%0,%1,%2,%3}, [%4];"
        : "=r"(r[0]), "=r"(r[1]), "=r"(r[2]), "=r"(r[3]) : "r"(addr));
}
__device__ __forceinline__ void ldsm4t(uint32_t* r, uint32_t addr) {
    asm volatile("ldmatrix.sync.aligned.m8n8.x4.trans.shared.b16 {%0,%1,%2,%3}, [%4];"
        : "=r"(r[0]), "=r"(r[1]), "=r"(r[2]), "=r"(r[3]) : "r"(addr));
}
// fp16 MMA, fp32 accumulate
__device__ __forceinline__ void mma_f16(float* d, const uint32_t* a,
                                        const uint32_t* b) {
    asm volatile("mma.sync.aligned.m16n8k16.row.col.f32.f16.f16.f32 "
        "{%0,%1,%2,%3}, {%4,%5,%6,%7}, {%8,%9}, {%0,%1,%2,%3};"
        : "+f"(d[0]), "+f"(d[1]), "+f"(d[2]), "+f"(d[3])
        : "r"(a[0]), "r"(a[1]), "r"(a[2]), "r"(a[3]), "r"(b[0]), "r"(b[1]));
}
// pack two fp32 -> half2 (first arg in low half)
__device__ __forceinline__ uint32_t packh(float lo, float hi) {
    __half2 h = __floats2half2_rn(lo, hi);
    return *reinterpret_cast<uint32_t*>(&h);
}

// exp2 via FFMA poly (no MUFU). z expected <= 0; clamped at -40.
__device__ __forceinline__ float fast_exp2(float z) {
    z = fmaxf(z, -40.f);
    const float km = z + 12582912.f;          // round-to-nearest int
    const int   ki = __float_as_int(km) - 0x4B400000;   // = round(z)
    const float f  = z - (km - 12582912.f);   // frac in [-0.5, 0.5]
    float p = 0.0013333558f;
    p = fmaf(p, f, 0.0096181815f);
    p = fmaf(p, f, 0.0555041087f);
    p = fmaf(p, f, 0.2402265069f);
    p = fmaf(p, f, 0.6931471806f);
    p = fmaf(p, f, 1.0f);
    return p * __int_as_float((ki + 127) << 23);
}

#define SCQ   0.18033688011112042f   // hd^-0.5 * log2(e), folded into Q
#define WSC   32.0f                  // W pre-scale (keeps W_lo in fp16 normal range)
#define IWSC  0.03125f

// ---------------------------------------------------------------------------
// Convert fp32 -> fp16 (activations; single precision level)
// ---------------------------------------------------------------------------
__global__ __launch_bounds__(256) void conv_x_kernel(
    const float* __restrict__ src, __half* __restrict__ dst, int n)
{
    int i = (blockIdx.x * 256 + threadIdx.x) * 4;
    if (i >= n) return;
    float4 v = *(const float4*)(src + i);
    uint2 o;
    o.x = packh(v.x, v.y);
    o.y = packh(v.z, v.w);
    *(uint2*)(dst + i) = o;
}

// ---------------------------------------------------------------------------
// Transpose + scale(x32) + split: W[1024, N] fp32 -> Wt_hi/lo [N, 1024] fp16
// ---------------------------------------------------------------------------
__global__ __launch_bounds__(256) void conv_wt_kernel(
    const float* __restrict__ W, __half* __restrict__ hi,
    __half* __restrict__ lo, int N)
{
    __shared__ float t[32][33];
    const int n0 = blockIdx.x * 32, k0 = blockIdx.y * 32;
    const int tx = threadIdx.x & 31, ty = threadIdx.x >> 5;
    #pragma unroll
    for (int i = 0; i < 4; i++)
        t[ty + i * 8][tx] = W[(size_t)(k0 + ty + i * 8) * N + n0 + tx];
    __syncthreads();
    #pragma unroll
    for (int i = 0; i < 4; i++) {
        const int n = n0 + ty + i * 8;
        const float v = t[tx][ty + i * 8] * WSC;
        __half h = __float2half_rn(v);
        hi[(size_t)n * DM + k0 + tx] = h;
        lo[(size_t)n * DM + k0 + tx] = __float2half_rn(v - __half2float(h));
    }
}

// ---------------------------------------------------------------------------
// HMMA fp16 2-product GEMM: D = A * (B_hi + B_lo)^T, A fp16 single level.
// 128x128 CTA tile, 8 warps (4m x 2n), m16n8k16, K-chunk 16, 4-stage
// single-sync cp.async pipeline. Stage = 3 arrays x 128 rows x 48B = 18432B;
// 4 stages = 72KB -> 2 CTAs/SM.
// DO_QKV: fused RoPE + 1/32 rescale + fp16 scatter (q hi; k,v hi+lo).
// ---------------------------------------------------------------------------
#define GST   18432
#define GARR  6144
template<int DO_QKV>
__global__ __launch_bounds__(256, 2) void hmma_gemm_kernel(
    const __half* __restrict__ A,
    const __half* __restrict__ Bhi, const __half* __restrict__ Blo,
    const float* __restrict__ rc, const float* __restrict__ rs,
    float* __restrict__ outp)
{
    extern __shared__ char smem[];
    const uint32_t sb = smem_u32(smem);
    const int tid = threadIdx.x, lane = tid & 31, wid = tid >> 5;
    const int wm = wid >> 1, wn = wid & 1;
    const int row0 = blockIdx.y * 128, col0 = blockIdx.x * 128;

    float acc[2][8][4];
    #pragma unroll
    for (int m = 0; m < 2; m++)
        #pragma unroll
        for (int n = 0; n < 8; n++)
            #pragma unroll
            for (int q = 0; q < 4; q++) acc[m][n][q] = 0.f;

    const int lrow = tid >> 1, kh = tid & 1;
    const __half* ga[3];
    ga[0] = A   + (size_t)(row0 + lrow) * DM + kh * 8;
    ga[1] = Bhi + (size_t)(col0 + lrow) * DM + kh * 8;
    ga[2] = Blo + (size_t)(col0 + lrow) * DM + kh * 8;
    const uint32_t ldst = lrow * 48 + kh * 16;

    auto issue = [&](int c) {
        const uint32_t buf = sb + (c & 3) * GST;
        const int k0 = c * 16;
        #pragma unroll
        for (int a = 0; a < 3; a++)
            cp16(buf + a * GARR + ldst, ga[a] + k0);
    };

    issue(0); CP_COMMIT();
    issue(1); CP_COMMIT();
    issue(2); CP_COMMIT();

    const uint32_t aoff = (uint32_t)((wm * 32 + (lane & 15)) * 48
                        + (lane >> 4) * 16);
    const uint32_t boff = (uint32_t)(GARR
                        + (wn * 64 + (lane & 7) + ((lane >> 4) << 3)) * 48
                        + ((lane >> 3) & 1) * 16);

    for (int c = 0; c < 64; c++) {
        CP_WAIT2();
        __syncthreads();
        if (c + 3 < 64) issue(c + 3);
        CP_COMMIT();
        const uint32_t buf = sb + (c & 3) * GST;
        const uint32_t ab = buf + aoff;
        const uint32_t bb = buf + boff;
        uint32_t ah[2][4];
        ldsm4(ah[0], ab);
        ldsm4(ah[1], ab + 16 * 48);
        #pragma unroll
        for (int nf2 = 0; nf2 < 4; nf2++) {
            uint32_t bh4[4], bl4[4];
            ldsm4(bh4, bb + nf2 * 16 * 48);
            ldsm4(bl4, bb + GARR + nf2 * 16 * 48);
            #pragma unroll
            for (int mt = 0; mt < 2; mt++) {
                mma_f16(acc[mt][2 * nf2],     ah[mt], bh4);
                mma_f16(acc[mt][2 * nf2],     ah[mt], bl4);
                mma_f16(acc[mt][2 * nf2 + 1], ah[mt], bh4 + 2);
                mma_f16(acc[mt][2 * nf2 + 1], ah[mt], bl4 + 2);
            }
        }
    }

    // ---------------- epilogue ----------------
    const int l4 = lane >> 2, l2 = (lane & 3) * 2;
    if (DO_QKV) {
        const int part = col0 >> 10;                 // 0=q, 1=k, 2=v
        const int head = ((col0 & 1023) >> 6) + wn;
        __half* dhi = (part == 0) ? g_qh : (part == 1) ? g_kh : g_vh;
        __half* dlo = (part == 1) ? g_kl : g_vl;     // unused for q
        #pragma unroll
        for (int mt = 0; mt < 2; mt++) {
            #pragma unroll
            for (int rr = 0; rr < 2; rr++) {
                const int grow = row0 + wm * 32 + mt * 16 + l4 + rr * 8;
                const int b = grow >> 11, s = grow & 2047;
                const size_t obase = ((size_t)(b * NHEAD + head) * SLEN + s) * HD;
                const float* rcp = rc + s * 32;
                const float* rsp = rs + s * 32;
                #pragma unroll
                for (int nf = 0; nf < 8; nf++) {
                    const int d = nf * 8 + l2;
                    const float v1 = acc[mt][nf][rr * 2 + 0];
                    const float v2 = acc[mt][nf][rr * 2 + 1];
                    float ox, oy;
                    if (part < 2) {
                        const int pi = d >> 1;
                        const float cth = rcp[pi], sth = rsp[pi];
                        ox = v1 * cth - v2 * sth;
                        oy = v1 * sth + v2 * cth;
                    } else {
                        ox = v1; oy = v2;
                    }
                    if (part == 0) {
                        ox *= (SCQ * IWSC); oy *= (SCQ * IWSC);
                        *(uint32_t*)(dhi + obase + d) = packh(ox, oy);
                    } else {
                        ox *= IWSC; oy *= IWSC;
                        const uint32_t hb = packh(ox, oy);
                        const __half2 h2 = *reinterpret_cast<const __half2*>(&hb);
                        const uint32_t lb = packh(ox - __half2float(__low2half(h2)),
                                                  oy - __half2float(__high2half(h2)));
                        *(uint32_t*)(dhi + obase + d) = hb;
                        *(uint32_t*)(dlo + obase + d) = lb;
                    }
                }
            }
        }
    } else {
        #pragma unroll
        for (int mt = 0; mt < 2; mt++) {
            #pragma unroll
            for (int rr = 0; rr < 2; rr++) {
                const int grow = row0 + wm * 32 + mt * 16 + l4 + rr * 8;
                float* op = outp + (size_t)grow * DM + col0 + wn * 64 + l2;
                #pragma unroll
                for (int nf = 0; nf < 8; nf++) {
                    float2 o;
                    o.x = acc[mt][nf][rr * 2 + 0] * IWSC;
                    o.y = acc[mt][nf][rr * 2 + 1] * IWSC;
                    *(float2*)(op + nf * 8) = o;
                }
            }
        }
    }
}

// ---------------------------------------------------------------------------
// HMMA fp16 FlashAttention: BM=128 queries, KN=128 keys/tile, 256 thr.
// QK: q @ (k_hi + k_lo) (2 products). PV: p @ (v_hi + v_lo).
// FFMA exp2 softmax; P stays in registers. Diagonal-tile skips (exact).
// smem: 5 tiles (Q, Kh, Kl, Vh, Vl) of 128 x 72 fp16 (144B stride).
// ---------------------------------------------------------------------------
#define FTILE 18432          // 128*72*2 bytes
__global__ __launch_bounds__(256) void flash_hmma_kernel()
{
    extern __shared__ char fsm[];
    const uint32_t sb = smem_u32(fsm);
    const uint32_t Qt = sb;
    const uint32_t Kh = sb + 1 * FTILE, Kl = sb + 2 * FTILE;
    const uint32_t Vh = sb + 3 * FTILE, Vl = sb + 4 * FTILE;

    const int tid = threadIdx.x, lane = tid & 31, w = tid >> 5;
    const int qb = gridDim.x - 1 - blockIdx.x;      // long CTAs first
    const int q0 = qb * 128, bh = blockIdx.y;
    const size_t base = (size_t)bh * SLEN * HD;

    const __half *qg  = g_qh + base + (size_t)q0 * HD;
    const __half *khg = g_kh + base, *klg = g_kl + base;
    const __half *vhg = g_vh + base, *vlg = g_vl + base;

    auto ldpair = [&](uint32_t dh, uint32_t dl,
                      const __half* gh, const __half* gl) {
        #pragma unroll
        for (int kk = 0; kk < 4; kk++) {
            const int c = tid + kk * 256;
            const int row = c >> 3, q8 = c & 7;
            cp16(dh + row * 144 + q8 * 16, gh + row * 64 + q8 * 8);
            cp16(dl + row * 144 + q8 * 16, gl + row * 64 + q8 * 8);
        }
    };
    auto ldone = [&](uint32_t d, const __half* g) {
        #pragma unroll
        for (int kk = 0; kk < 4; kk++) {
            const int c = tid + kk * 256;
            const int row = c >> 3, q8 = c & 7;
            cp16(d + row * 144 + q8 * 16, g + row * 64 + q8 * 8);
        }
    };

    ldone(Qt, qg);
    ldpair(Kh, Kl, khg, klg);
    CP_COMMIT();
    ldpair(Vh, Vl, vhg, vlg);
    CP_COMMIT();

    uint32_t qf[4][4];
    float oacc[8][4];
    #pragma unroll
    for (int j = 0; j < 8; j++)
        #pragma unroll
        for (int q = 0; q < 4; q++) oacc[j][q] = 0.f;
    float m0 = -1e30f, m1 = -1e30f, l0 = 0.f, l1 = 0.f;

    const int nkb = qb + 1;
    for (int kb = 0; kb < nkb; kb++) {
        const bool lastt = (kb == nkb - 1);
        CP_WAIT1();
        __syncthreads();
        if (kb == 0) {
            #pragma unroll
            for (int ks = 0; ks < 4; ks++) {
                const uint32_t a = (uint32_t)((w * 16 + (lane & 15)) * 144
                                 + (ks * 16 + (lane >> 4) * 8) * 2);
                ldsm4(qf[ks], Qt + a);
            }
        }
        // ---- S = Q @ (K_hi + K_lo)^T ----
        float sacc[16][4];
        #pragma unroll
        for (int j = 0; j < 16; j++)
            #pragma unroll
            for (int q = 0; q < 4; q++) sacc[j][q] = 0.f;
        #pragma unroll
        for (int ks = 0; ks < 4; ks++) {
            #pragma unroll
            for (int p = 0; p < 8; p++) {
                if (lastt && p > w) continue;        // fully-masked col group
                uint32_t kh4[4], kl4[4];
                const uint32_t a = (uint32_t)((p * 16 + (lane & 15)) * 144
                                 + (ks * 16 + (lane >> 4) * 8) * 2);
                ldsm4(kh4, Kh + a);
                ldsm4(kl4, Kl + a);
                uint32_t bh0[2] = {kh4[0], kh4[2]}, bh1[2] = {kh4[1], kh4[3]};
                uint32_t bl0[2] = {kl4[0], kl4[2]}, bl1[2] = {kl4[1], kl4[3]};
                mma_f16(sacc[2 * p],     qf[ks], bh0);
                mma_f16(sacc[2 * p],     qf[ks], bl0);
                mma_f16(sacc[2 * p + 1], qf[ks], bh1);
                mma_f16(sacc[2 * p + 1], qf[ks], bl1);
            }
        }
        __syncthreads();                 // all warps done reading K smem
        if (!lastt) {
            ldpair(Kh, Kl, khg + (size_t)(kb + 1) * 128 * HD,
                           klg + (size_t)(kb + 1) * 128 * HD);
            CP_COMMIT();
        }

        // ---- softmax (registers only; overlaps with K prefetch) ----
        if (lastt) {  // diagonal tile: mask col > row (tile-local, kb*128==q0)
            const int rl0 = w * 16 + (lane >> 2);
            #pragma unroll
            for (int j = 0; j < 16; j++) {
                const int c = j * 8 + (lane & 3) * 2;
                if (c     > rl0)     sacc[j][0] = -1e30f;
                if (c + 1 > rl0)     sacc[j][1] = -1e30f;
                if (c     > rl0 + 8) sacc[j][2] = -1e30f;
                if (c + 1 > rl0 + 8) sacc[j][3] = -1e30f;
            }
        }
        float rmx0 = -1e30f, rmx1 = -1e30f;
        #pragma unroll
        for (int j = 0; j < 16; j++) {
            rmx0 = fmaxf(rmx0, fmaxf(sacc[j][0], sacc[j][1]));
            rmx1 = fmaxf(rmx1, fmaxf(sacc[j][2], sacc[j][3]));
        }
        rmx0 = fmaxf(rmx0, __shfl_xor_sync(0xffffffffu, rmx0, 1));
        rmx0 = fmaxf(rmx0, __shfl_xor_sync(0xffffffffu, rmx0, 2));
        rmx1 = fmaxf(rmx1, __shfl_xor_sync(0xffffffffu, rmx1, 1));
        rmx1 = fmaxf(rmx1, __shfl_xor_sync(0xffffffffu, rmx1, 2));
        const float mn0 = fmaxf(m0, rmx0), mn1 = fmaxf(m1, rmx1);
        const float rs0 = fast_exp2(m0 - mn0), rs1 = fast_exp2(m1 - mn1);
        m0 = mn0; m1 = mn1;
        float sum0 = 0.f, sum1 = 0.f;
        #pragma unroll
        for (int j = 0; j < 16; j++) {
            sacc[j][0] = fast_exp2(sacc[j][0] - m0);
            sacc[j][1] = fast_exp2(sacc[j][1] - m0);
            sacc[j][2] = fast_exp2(sacc[j][2] - m1);
            sacc[j][3] = fast_exp2(sacc[j][3] - m1);
            sum0 += sacc[j][0] + sacc[j][1];
            sum1 += sacc[j][2] + sacc[j][3];
        }
        sum0 += __shfl_xor_sync(0xffffffffu, sum0, 1);
        sum0 += __shfl_xor_sync(0xffffffffu, sum0, 2);
        sum1 += __shfl_xor_sync(0xffffffffu, sum1, 1);
        sum1 += __shfl_xor_sync(0xffffffffu, sum1, 2);
        l0 = l0 * rs0 + sum0;
        l1 = l1 * rs1 + sum1;
        #pragma unroll
        for (int j = 0; j < 8; j++) {
            oacc[j][0] *= rs0; oacc[j][1] *= rs0;
            oacc[j][2] *= rs1; oacc[j][3] *= rs1;
        }

        // ---- O += P @ (V_hi + V_lo) ----
        if (!lastt) CP_WAIT1(); else CP_WAIT0();
        __syncthreads();
        #pragma unroll
        for (int ks = 0; ks < 8; ks++) {
            if (lastt && ks > w) continue;           // P ~ 0 beyond diagonal
            const float* s0 = sacc[2 * ks];
            const float* s1 = sacc[2 * ks + 1];
            uint32_t ph[4];
            ph[0] = packh(s0[0], s0[1]); ph[1] = packh(s0[2], s0[3]);
            ph[2] = packh(s1[0], s1[1]); ph[3] = packh(s1[2], s1[3]);
            #pragma unroll
            for (int p = 0; p < 4; p++) {
                uint32_t vh4[4], vl4[4];
                const uint32_t a = (uint32_t)((ks * 16 + (lane & 15)) * 144
                                 + (p * 16 + (lane >> 4) * 8) * 2);
                ldsm4t(vh4, Vh + a);
                ldsm4t(vl4, Vl + a);
                uint32_t bh0[2] = {vh4[0], vh4[1]}, bh1[2] = {vh4[2], vh4[3]};
                uint32_t bl0[2] = {vl4[0], vl4[1]}, bl1[2] = {vl4[2], vl4[3]};
                mma_f16(oacc[2 * p],     ph, bh0);
                mma_f16(oacc[2 * p],     ph, bl0);
                mma_f16(oacc[2 * p + 1], ph, bh1);
                mma_f16(oacc[2 * p + 1], ph, bl1);
            }
        }
        __syncthreads();                 // all warps done reading V smem
        if (!lastt) {
            ldpair(Vh, Vl, vhg + (size_t)(kb + 1) * 128 * HD,
                           vlg + (size_t)(kb + 1) * 128 * HD);
            CP_COMMIT();
        }
    }

    // ---- epilogue: normalize, write fp16 [B,S,D] ----
    const float inv0 = 1.f / l0, inv1 = 1.f / l1;
    const int b = bh >> 4, h = bh & 15;
    const int s0r = q0 + w * 16 + (lane >> 2);
    const size_t rowA = (size_t)(b * SLEN + s0r);
    const size_t rowB = rowA + 8;
    const int colb = h * 64 + (lane & 3) * 2;
    #pragma unroll
    for (int j = 0; j < 8; j++) {
        const int col = colb + j * 8;
        *(uint32_t*)(g_ah + rowA * DM + col) =
            packh(oacc[j][0] * inv0, oacc[j][1] * inv0);
        *(uint32_t*)(g_ah + rowB * DM + col) =
            packh(oacc[j][2] * inv1, oacc[j][3] * inv1);
    }
}

// ---------------------------------------------------------------------------
extern "C" void kernel_launch(void* const* d_in, const int* in_sizes, int n_in,
                              void* d_out, int out_size)
{
    const float* x    = (const float*)d_in[0];
    const float* rc   = (const float*)d_in[1];
    const float* rs   = (const float*)d_in[2];
    const float* Wqkv = (const float*)d_in[3];
    const float* Wout = (const float*)d_in[4];
    float* out = (float*)d_out;

    const size_t mma_sh   = 4 * GST;     // 73728
    const size_t flash_sh = 5 * FTILE;   // 92160
    cudaFuncSetAttribute(hmma_gemm_kernel<1>,
        cudaFuncAttributeMaxDynamicSharedMemorySize, (int)mma_sh);
    cudaFuncSetAttribute(hmma_gemm_kernel<0>,
        cudaFuncAttributeMaxDynamicSharedMemorySize, (int)mma_sh);
    cudaFuncSetAttribute(flash_hmma_kernel,
        cudaFuncAttributeMaxDynamicSharedMemorySize, (int)flash_sh);

    __half *xh, *ah, *wqh, *wql, *woh, *wol;
    cudaGetSymbolAddress((void**)&xh,  g_xh);
    cudaGetSymbolAddress((void**)&ah,  g_ah);
    cudaGetSymbolAddress((void**)&wqh, g_wqh);
    cudaGetSymbolAddress((void**)&wql, g_wql);
    cudaGetSymbolAddress((void**)&woh, g_woh);
    cudaGetSymbolAddress((void**)&wol, g_wol);

    // 1. converts / transposes
    conv_x_kernel<<<(NROWS * DM) / 1024, 256>>>(x, xh, NROWS * DM);
    conv_wt_kernel<<<dim3(96, 32), 256>>>(Wqkv, wqh, wql, 3 * DM);
    conv_wt_kernel<<<dim3(32, 32), 256>>>(Wout, woh, wol, DM);

    // 2. QKV GEMM (fp16 HMMA) + fused RoPE + scatter
    hmma_gemm_kernel<1><<<dim3(24, 32), 256, mma_sh>>>(
        xh, wqh, wql, rc, rs, nullptr);

    // 3. flash attention (fp16 HMMA) -> g_ah
    flash_hmma_kernel<<<dim3(SLEN / 128, BATCH * NHEAD), 256, flash_sh>>>();

    // 4. out-projection GEMM (fp16 HMMA)
    hmma_gemm_kernel<0><<<dim3(8, 32), 256, mma_sh>>>(
        ah, woh, wol, nullptr, nullptr, out);
}